// round 1
// baseline (speedup 1.0000x reference)
#include <cuda_runtime.h>

#define H 128
#define GPITCH 132          // smem pitch (floats), keeps float4 alignment, breaks conflicts
#define VMAX 50048
#define DMAX 20096

// Scratch (static device globals -- no allocation allowed)
__device__ float g_buf1[(size_t)VMAX * H];
__device__ float g_buf2[(size_t)VMAX * H];
__device__ float g_doc [(size_t)DMAX * H];

// ---------------------------------------------------------------------------
// Zero-fill (float4)
// ---------------------------------------------------------------------------
__global__ void zero_kernel(float* __restrict__ p, int n4) {
    int i = blockIdx.x * blockDim.x + threadIdx.x;
    float4 z = make_float4(0.f, 0.f, 0.f, 0.f);
    for (; i < n4; i += gridDim.x * blockDim.x)
        ((float4*)p)[i] = z;
}

// ---------------------------------------------------------------------------
// SpMM via scatter-atomics: dst[row[e]] += val[e] * src[col[e]]
// One warp per edge; each lane handles 4 floats via one vector RED.
// ---------------------------------------------------------------------------
__global__ void spmm_atomic_kernel(const int* __restrict__ row,
                                   const int* __restrict__ col,
                                   const float* __restrict__ val,
                                   const float* __restrict__ src,
                                   float* __restrict__ dst, int nnz) {
    int w = (blockIdx.x * blockDim.x + threadIdx.x) >> 5;
    if (w >= nnz) return;
    int lane = threadIdx.x & 31;
    int r = __ldg(row + w);
    int c = __ldg(col + w);
    float v = __ldg(val + w);
    float4 s = ((const float4*)(src + (size_t)c * H))[lane];
    float4* d = ((float4*)(dst + (size_t)r * H)) + lane;
    asm volatile("red.global.add.v4.f32 [%0], {%1, %2, %3, %4};"
                 :: "l"(d), "f"(v * s.x), "f"(v * s.y), "f"(v * s.z), "f"(v * s.w)
                 : "memory");
}

// ---------------------------------------------------------------------------
// GEMM mainloop: out-tile = A[row0:row0+128, 0:128] @ W^T   (W is [128,128])
// 256 threads, each computes an 8x8 micro-tile; both tiles transposed in smem.
// ---------------------------------------------------------------------------
__device__ __forceinline__ void gemm_mainloop(const float* __restrict__ A, int nrows, int row0,
                                              const float* __restrict__ W,
                                              float* sA, float* sW,
                                              float acc[8][8]) {
    int tid = threadIdx.x;
#pragma unroll
    for (int it = 0; it < 16; ++it) {
        int idx = it * 256 + tid;     // 0..4095
        int r   = idx & 127;          // row within tile (or W row = out col)
        int k4  = idx >> 7;           // 0..31 (float4 index along k)
        int grow = row0 + r;
        float4 a = make_float4(0.f, 0.f, 0.f, 0.f);
        if (grow < nrows) a = *(const float4*)(A + (size_t)grow * H + k4 * 4);
        sA[(4 * k4 + 0) * GPITCH + r] = a.x;
        sA[(4 * k4 + 1) * GPITCH + r] = a.y;
        sA[(4 * k4 + 2) * GPITCH + r] = a.z;
        sA[(4 * k4 + 3) * GPITCH + r] = a.w;
        float4 wv = *(const float4*)(W + (size_t)r * H + k4 * 4);
        sW[(4 * k4 + 0) * GPITCH + r] = wv.x;
        sW[(4 * k4 + 1) * GPITCH + r] = wv.y;
        sW[(4 * k4 + 2) * GPITCH + r] = wv.z;
        sW[(4 * k4 + 3) * GPITCH + r] = wv.w;
    }
    __syncthreads();

    int tx = tid & 15, ty = tid >> 4;
#pragma unroll 4
    for (int k = 0; k < H; ++k) {
        const float* pa = sA + k * GPITCH + (ty << 3);
        const float* pb = sW + k * GPITCH + (tx << 3);
        float4 a0 = *(const float4*)(pa);
        float4 a1 = *(const float4*)(pa + 4);
        float4 b0 = *(const float4*)(pb);
        float4 b1 = *(const float4*)(pb + 4);
        float av[8] = {a0.x, a0.y, a0.z, a0.w, a1.x, a1.y, a1.z, a1.w};
        float bv[8] = {b0.x, b0.y, b0.z, b0.w, b1.x, b1.y, b1.z, b1.w};
#pragma unroll
        for (int i = 0; i < 8; ++i)
#pragma unroll
            for (int j = 0; j < 8; ++j)
                acc[i][j] += av[i] * bv[j];
    }
}

__device__ __forceinline__ float red16(float v) {
#pragma unroll
    for (int off = 8; off > 0; off >>= 1)
        v += __shfl_xor_sync(0xffffffffu, v, off, 16);
    return v;
}

// out = relu(A @ W^T)
__global__ void gemm_relu_kernel(const float* __restrict__ A, const float* __restrict__ W,
                                 float* __restrict__ out, int nrows) {
    extern __shared__ float smem[];
    float* sA = smem;
    float* sW = smem + H * GPITCH;
    float acc[8][8];
#pragma unroll
    for (int i = 0; i < 8; ++i)
#pragma unroll
        for (int j = 0; j < 8; ++j) acc[i][j] = 0.f;

    int row0 = blockIdx.x * 128;
    gemm_mainloop(A, nrows, row0, W, sA, sW, acc);

    int tid = threadIdx.x, tx = tid & 15, ty = tid >> 4;
#pragma unroll
    for (int i = 0; i < 8; ++i) {
        int grow = row0 + (ty << 3) + i;
        if (grow < nrows) {
            float4 o0, o1;
            o0.x = fmaxf(acc[i][0], 0.f); o0.y = fmaxf(acc[i][1], 0.f);
            o0.z = fmaxf(acc[i][2], 0.f); o0.w = fmaxf(acc[i][3], 0.f);
            o1.x = fmaxf(acc[i][4], 0.f); o1.y = fmaxf(acc[i][5], 0.f);
            o1.z = fmaxf(acc[i][6], 0.f); o1.w = fmaxf(acc[i][7], 0.f);
            *(float4*)(out + (size_t)grow * H + (tx << 3))     = o0;
            *(float4*)(out + (size_t)grow * H + (tx << 3) + 4) = o1;
        }
    }
}

// wordsum = layernorm(0.3*emb + 0.7*relu(A @ W^T)) * g + b + emb
__global__ void gemm_ln_kernel(const float* __restrict__ A, const float* __restrict__ W,
                               const float* __restrict__ emb,
                               const float* __restrict__ ng, const float* __restrict__ nb,
                               float* __restrict__ out, int nrows) {
    extern __shared__ float smem[];
    float* sA = smem;
    float* sW = smem + H * GPITCH;
    float acc[8][8];
#pragma unroll
    for (int i = 0; i < 8; ++i)
#pragma unroll
        for (int j = 0; j < 8; ++j) acc[i][j] = 0.f;

    int row0 = blockIdx.x * 128;
    gemm_mainloop(A, nrows, row0, W, sA, sW, acc);

    int tid = threadIdx.x, tx = tid & 15, ty = tid >> 4;
    int c0 = tx << 3;
    float4 g0 = *(const float4*)(ng + c0);
    float4 g1 = *(const float4*)(ng + c0 + 4);
    float4 bb0 = *(const float4*)(nb + c0);
    float4 bb1 = *(const float4*)(nb + c0 + 4);
    float gv[8] = {g0.x, g0.y, g0.z, g0.w, g1.x, g1.y, g1.z, g1.w};
    float bv[8] = {bb0.x, bb0.y, bb0.z, bb0.w, bb1.x, bb1.y, bb1.z, bb1.w};

#pragma unroll
    for (int i = 0; i < 8; ++i) {
        int grow = row0 + (ty << 3) + i;
        bool valid = (grow < nrows);
        float4 e0 = make_float4(0.f, 0.f, 0.f, 0.f), e1 = e0;
        if (valid) {
            e0 = *(const float4*)(emb + (size_t)grow * H + c0);
            e1 = *(const float4*)(emb + (size_t)grow * H + c0 + 4);
        }
        float ev[8] = {e0.x, e0.y, e0.z, e0.w, e1.x, e1.y, e1.z, e1.w};
        float h[8];
        float s = 0.f;
#pragma unroll
        for (int j = 0; j < 8; ++j) {
            h[j] = 0.3f * ev[j] + 0.7f * fmaxf(acc[i][j], 0.f);
            s += h[j];
        }
        float mu = red16(s) * (1.f / 128.f);
        float ss = 0.f;
#pragma unroll
        for (int j = 0; j < 8; ++j) {
            h[j] -= mu;
            ss += h[j] * h[j];
        }
        float var = red16(ss) * (1.f / 128.f);
        float rstd = rsqrtf(var + 1e-5f);
        if (valid) {
            float o[8];
#pragma unroll
            for (int j = 0; j < 8; ++j)
                o[j] = h[j] * rstd * gv[j] + bv[j] + ev[j];
            *(float4*)(out + (size_t)grow * H + c0)     = make_float4(o[0], o[1], o[2], o[3]);
            *(float4*)(out + (size_t)grow * H + c0 + 4) = make_float4(o[4], o[5], o[6], o[7]);
        }
    }
}

// logits = relu(A @ mlpW^T + mlp_b) @ clfW^T + clf_b
__global__ void gemm_clf_kernel(const float* __restrict__ A, const float* __restrict__ W,
                                const float* __restrict__ mlp_b,
                                const float* __restrict__ clf_W, const float* __restrict__ clf_b,
                                float* __restrict__ out, int nrows) {
    extern __shared__ float smem[];
    float* sA = smem;
    float* sW = smem + H * GPITCH;
    float acc[8][8];
#pragma unroll
    for (int i = 0; i < 8; ++i)
#pragma unroll
        for (int j = 0; j < 8; ++j) acc[i][j] = 0.f;

    int row0 = blockIdx.x * 128;
    gemm_mainloop(A, nrows, row0, W, sA, sW, acc);

    int tid = threadIdx.x, tx = tid & 15, ty = tid >> 4;
    int c0 = tx << 3;
    float4 mb0 = *(const float4*)(mlp_b + c0);
    float4 mb1 = *(const float4*)(mlp_b + c0 + 4);
    float bias[8] = {mb0.x, mb0.y, mb0.z, mb0.w, mb1.x, mb1.y, mb1.z, mb1.w};
    float4 w00 = *(const float4*)(clf_W + c0);
    float4 w01 = *(const float4*)(clf_W + c0 + 4);
    float4 w10 = *(const float4*)(clf_W + H + c0);
    float4 w11 = *(const float4*)(clf_W + H + c0 + 4);
    float cv0[8] = {w00.x, w00.y, w00.z, w00.w, w01.x, w01.y, w01.z, w01.w};
    float cv1[8] = {w10.x, w10.y, w10.z, w10.w, w11.x, w11.y, w11.z, w11.w};
    float cb0 = __ldg(clf_b), cb1 = __ldg(clf_b + 1);

#pragma unroll
    for (int i = 0; i < 8; ++i) {
        int grow = row0 + (ty << 3) + i;
        float p0 = 0.f, p1 = 0.f;
#pragma unroll
        for (int j = 0; j < 8; ++j) {
            float hv = fmaxf(acc[i][j] + bias[j], 0.f);
            p0 += hv * cv0[j];
            p1 += hv * cv1[j];
        }
        p0 = red16(p0);
        p1 = red16(p1);
        if (tx == 0 && grow < nrows) {
            out[(size_t)grow * 2 + 0] = p0 + cb0;
            out[(size_t)grow * 2 + 1] = p1 + cb1;
        }
    }
}

// ---------------------------------------------------------------------------
// Host launcher
// ---------------------------------------------------------------------------
extern "C" void kernel_launch(void* const* d_in, const int* in_sizes, int n_in,
                              void* d_out, int out_size) {
    const int*   A_row  = (const int*)d_in[0];
    const int*   A_col  = (const int*)d_in[1];
    const float* A_val  = (const float*)d_in[2];
    const int*   X_row  = (const int*)d_in[3];
    const int*   X_col  = (const int*)d_in[4];
    const float* X_val  = (const float*)d_in[5];
    const float* emb_W  = (const float*)d_in[6];
    const float* lin1_W = (const float*)d_in[7];
    const float* lin2_W = (const float*)d_in[8];
    const float* norm_g = (const float*)d_in[9];
    const float* norm_b = (const float*)d_in[10];
    const float* mlp_W  = (const float*)d_in[11];
    const float* mlp_b  = (const float*)d_in[12];
    const float* clf_W  = (const float*)d_in[13];
    const float* clf_b  = (const float*)d_in[14];
    float* out = (float*)d_out;

    int E    = in_sizes[0];
    int NNZ  = in_sizes[3];
    int V    = in_sizes[6] / H;
    int NDOC = out_size / 2;

    float *b1, *b2, *dc;
    cudaGetSymbolAddress((void**)&b1, g_buf1);
    cudaGetSymbolAddress((void**)&b2, g_buf2);
    cudaGetSymbolAddress((void**)&dc, g_doc);

    size_t smem = (size_t)2 * H * GPITCH * sizeof(float);   // 135168 B
    cudaFuncSetAttribute(gemm_relu_kernel, cudaFuncAttributeMaxDynamicSharedMemorySize, (int)smem);
    cudaFuncSetAttribute(gemm_ln_kernel,   cudaFuncAttributeMaxDynamicSharedMemorySize, (int)smem);
    cudaFuncSetAttribute(gemm_clf_kernel,  cudaFuncAttributeMaxDynamicSharedMemorySize, (int)smem);

    int vn4 = V * H / 4;
    int dn4 = NDOC * H / 4;
    int vblocks = (V + 127) / 128;
    int dblocks = (NDOC + 127) / 128;
    int spmmA_blocks = (int)(((long long)E * 32 + 255) / 256);
    int spmmX_blocks = (int)(((long long)NNZ * 32 + 255) / 256);

    // 1) Hx1 = A @ emb
    zero_kernel<<<(vn4 + 255) / 256, 256>>>(b1, vn4);
    spmm_atomic_kernel<<<spmmA_blocks, 256>>>(A_row, A_col, A_val, emb_W, b1, E);
    // 2) Hx1 = relu(Hx1 @ lin1^T)
    gemm_relu_kernel<<<vblocks, 256, smem>>>(b1, lin1_W, b2, V);
    // 3) Hx2 = A @ Hx1
    zero_kernel<<<(vn4 + 255) / 256, 256>>>(b1, vn4);
    spmm_atomic_kernel<<<spmmA_blocks, 256>>>(A_row, A_col, A_val, b2, b1, E);
    // 4) wordsum = LN(0.3*emb + 0.7*relu(Hx2 @ lin2^T))*g + b + emb
    gemm_ln_kernel<<<vblocks, 256, smem>>>(b1, lin2_W, emb_W, norm_g, norm_b, b2, V);
    // 5) doc = X @ wordsum
    zero_kernel<<<(dn4 + 255) / 256, 256>>>(dc, dn4);
    spmm_atomic_kernel<<<spmmX_blocks, 256>>>(X_row, X_col, X_val, b2, dc, NNZ);
    // 6) logits = relu(doc @ mlp^T + mlp_b) @ clf^T + clf_b
    gemm_clf_kernel<<<dblocks, 256, smem>>>(dc, mlp_W, mlp_b, clf_W, clf_b, out, NDOC);
}

// round 2
// speedup vs baseline: 1.5326x; 1.5326x over previous
#include <cuda_runtime.h>

#define H 128
#define GPITCH 132
#define VMAX 50048
#define DMAX 20096
#define EMAX 1600512

// ---------------- static scratch (no allocation allowed) -------------------
__device__ float g_buf1[(size_t)VMAX * H];
__device__ float g_buf2[(size_t)VMAX * H];
__device__ float g_doc [(size_t)DMAX * H];

__device__ int   gA_ptr[VMAX + 1];
__device__ int   gA_cur[VMAX + 1];
__device__ int   gA_col[EMAX];
__device__ float gA_val[EMAX];
__device__ int   gX_ptr[DMAX + 1];
__device__ int   gX_cur[DMAX + 1];
__device__ int   gX_col[EMAX];
__device__ float gX_val[EMAX];
__device__ int   g_bsum[2][64];

// ---------------------------------------------------------------------------
// Counting sort: zero / hist / 3-step scan / scatter
// ---------------------------------------------------------------------------
__global__ void zero_int_kernel(int* __restrict__ p, int n) {
    int i = blockIdx.x * blockDim.x + threadIdx.x;
    if (i < n) p[i] = 0;
}

__global__ void hist_kernel(const int* __restrict__ row, int nnz, int* __restrict__ cnt) {
    int i = blockIdx.x * blockDim.x + threadIdx.x;
    if (i < nnz) atomicAdd(cnt + __ldg(row + i), 1);
}

// per-1024-block exclusive scan; cnt and out may alias different arrays
__global__ void scan1_kernel(const int* __restrict__ cnt, int* __restrict__ out,
                             int* __restrict__ bsum, int n) {
    __shared__ int s[1024];
    int i = blockIdx.x * 1024 + threadIdx.x;
    int v = (i < n) ? cnt[i] : 0;
    s[threadIdx.x] = v;
    __syncthreads();
#pragma unroll
    for (int off = 1; off < 1024; off <<= 1) {
        int t = (threadIdx.x >= off) ? s[threadIdx.x - off] : 0;
        __syncthreads();
        s[threadIdx.x] += t;
        __syncthreads();
    }
    if (i < n) out[i] = s[threadIdx.x] - v;           // exclusive
    if (threadIdx.x == 1023) bsum[blockIdx.x] = s[1023];
}

// single-block exclusive scan over block sums (<=64 entries)
__global__ void scan2_kernel(int* __restrict__ bsum, int nb) {
    __shared__ int s[64];
    int t = threadIdx.x;
    int v = (t < nb) ? bsum[t] : 0;
    s[t] = v;
    __syncthreads();
#pragma unroll
    for (int off = 1; off < 64; off <<= 1) {
        int u = (t >= off) ? s[t - off] : 0;
        __syncthreads();
        s[t] += u;
        __syncthreads();
    }
    if (t < nb) bsum[t] = s[t] - v;                   // exclusive
}

// add block offsets, duplicate into cursor array, write ptr[n]=nnz
__global__ void scan3_kernel(int* __restrict__ ptr, int* __restrict__ cur,
                             const int* __restrict__ bsum, int n, int nnz) {
    int i = blockIdx.x * 1024 + threadIdx.x;
    if (i < n) {
        int p = ptr[i] + bsum[blockIdx.x];
        ptr[i] = p;
        cur[i] = p;
    }
    if (i == 0) { ptr[n] = nnz; cur[n] = nnz; }
}

__global__ void scatter_kernel(const int* __restrict__ row, const int* __restrict__ col,
                               const float* __restrict__ val, int nnz,
                               int* __restrict__ cur,
                               int* __restrict__ scol, float* __restrict__ sval) {
    int e = blockIdx.x * blockDim.x + threadIdx.x;
    if (e < nnz) {
        int r = __ldg(row + e);
        int p = atomicAdd(cur + r, 1);
        scol[p] = __ldg(col + e);
        sval[p] = __ldg(val + e);
    }
}

// ---------------------------------------------------------------------------
// Gather SpMM over CSR: one warp per output row, float4 accumulator per lane.
// ---------------------------------------------------------------------------
__global__ void spmm_csr_kernel(const int* __restrict__ ptr, const int* __restrict__ cols,
                                const float* __restrict__ vals, const float* __restrict__ src,
                                float* __restrict__ dst, int nrows) {
    int w = (blockIdx.x * blockDim.x + threadIdx.x) >> 5;
    if (w >= nrows) return;
    int lane = threadIdx.x & 31;
    int beg = __ldg(ptr + w);
    int end = __ldg(ptr + w + 1);
    float4 acc = make_float4(0.f, 0.f, 0.f, 0.f);
    for (int base = beg; base < end; base += 32) {
        int n = min(32, end - base);
        int c = 0; float v = 0.f;
        if (base + lane < end) {
            c = __ldg(cols + base + lane);
            v = __ldg(vals + base + lane);
        }
        int j = 0;
        // full-throttle unrolled body: 4 independent gathers in flight
        for (; j + 4 <= n; j += 4) {
            int   c0 = __shfl_sync(0xffffffffu, c, j + 0);
            int   c1 = __shfl_sync(0xffffffffu, c, j + 1);
            int   c2 = __shfl_sync(0xffffffffu, c, j + 2);
            int   c3 = __shfl_sync(0xffffffffu, c, j + 3);
            float v0 = __shfl_sync(0xffffffffu, v, j + 0);
            float v1 = __shfl_sync(0xffffffffu, v, j + 1);
            float v2 = __shfl_sync(0xffffffffu, v, j + 2);
            float v3 = __shfl_sync(0xffffffffu, v, j + 3);
            float4 s0 = ((const float4*)(src + (size_t)c0 * H))[lane];
            float4 s1 = ((const float4*)(src + (size_t)c1 * H))[lane];
            float4 s2 = ((const float4*)(src + (size_t)c2 * H))[lane];
            float4 s3 = ((const float4*)(src + (size_t)c3 * H))[lane];
            acc.x += v0 * s0.x; acc.y += v0 * s0.y; acc.z += v0 * s0.z; acc.w += v0 * s0.w;
            acc.x += v1 * s1.x; acc.y += v1 * s1.y; acc.z += v1 * s1.z; acc.w += v1 * s1.w;
            acc.x += v2 * s2.x; acc.y += v2 * s2.y; acc.z += v2 * s2.z; acc.w += v2 * s2.w;
            acc.x += v3 * s3.x; acc.y += v3 * s3.y; acc.z += v3 * s3.z; acc.w += v3 * s3.w;
        }
        for (; j < n; ++j) {
            int   cj = __shfl_sync(0xffffffffu, c, j);
            float vj = __shfl_sync(0xffffffffu, v, j);
            float4 s = ((const float4*)(src + (size_t)cj * H))[lane];
            acc.x += vj * s.x; acc.y += vj * s.y; acc.z += vj * s.z; acc.w += vj * s.w;
        }
    }
    ((float4*)(dst + (size_t)w * H))[lane] = acc;
}

// ---------------------------------------------------------------------------
// GEMM mainloop (unchanged from R1): 128x128 tile, 256 thr, 8x8 micro-tiles
// ---------------------------------------------------------------------------
__device__ __forceinline__ void gemm_mainloop(const float* __restrict__ A, int nrows, int row0,
                                              const float* __restrict__ W,
                                              float* sA, float* sW,
                                              float acc[8][8]) {
    int tid = threadIdx.x;
#pragma unroll
    for (int it = 0; it < 16; ++it) {
        int idx = it * 256 + tid;
        int r   = idx & 127;
        int k4  = idx >> 7;
        int grow = row0 + r;
        float4 a = make_float4(0.f, 0.f, 0.f, 0.f);
        if (grow < nrows) a = *(const float4*)(A + (size_t)grow * H + k4 * 4);
        sA[(4 * k4 + 0) * GPITCH + r] = a.x;
        sA[(4 * k4 + 1) * GPITCH + r] = a.y;
        sA[(4 * k4 + 2) * GPITCH + r] = a.z;
        sA[(4 * k4 + 3) * GPITCH + r] = a.w;
        float4 wv = *(const float4*)(W + (size_t)r * H + k4 * 4);
        sW[(4 * k4 + 0) * GPITCH + r] = wv.x;
        sW[(4 * k4 + 1) * GPITCH + r] = wv.y;
        sW[(4 * k4 + 2) * GPITCH + r] = wv.z;
        sW[(4 * k4 + 3) * GPITCH + r] = wv.w;
    }
    __syncthreads();

    int tx = tid & 15, ty = tid >> 4;
#pragma unroll 4
    for (int k = 0; k < H; ++k) {
        const float* pa = sA + k * GPITCH + (ty << 3);
        const float* pb = sW + k * GPITCH + (tx << 3);
        float4 a0 = *(const float4*)(pa);
        float4 a1 = *(const float4*)(pa + 4);
        float4 b0 = *(const float4*)(pb);
        float4 b1 = *(const float4*)(pb + 4);
        float av[8] = {a0.x, a0.y, a0.z, a0.w, a1.x, a1.y, a1.z, a1.w};
        float bv[8] = {b0.x, b0.y, b0.z, b0.w, b1.x, b1.y, b1.z, b1.w};
#pragma unroll
        for (int i = 0; i < 8; ++i)
#pragma unroll
            for (int j = 0; j < 8; ++j)
                acc[i][j] += av[i] * bv[j];
    }
}

__device__ __forceinline__ float red16(float v) {
#pragma unroll
    for (int off = 8; off > 0; off >>= 1)
        v += __shfl_xor_sync(0xffffffffu, v, off, 16);
    return v;
}

__global__ void gemm_relu_kernel(const float* __restrict__ A, const float* __restrict__ W,
                                 float* __restrict__ out, int nrows) {
    extern __shared__ float smem[];
    float* sA = smem;
    float* sW = smem + H * GPITCH;
    float acc[8][8];
#pragma unroll
    for (int i = 0; i < 8; ++i)
#pragma unroll
        for (int j = 0; j < 8; ++j) acc[i][j] = 0.f;

    int row0 = blockIdx.x * 128;
    gemm_mainloop(A, nrows, row0, W, sA, sW, acc);

    int tid = threadIdx.x, tx = tid & 15, ty = tid >> 4;
#pragma unroll
    for (int i = 0; i < 8; ++i) {
        int grow = row0 + (ty << 3) + i;
        if (grow < nrows) {
            float4 o0, o1;
            o0.x = fmaxf(acc[i][0], 0.f); o0.y = fmaxf(acc[i][1], 0.f);
            o0.z = fmaxf(acc[i][2], 0.f); o0.w = fmaxf(acc[i][3], 0.f);
            o1.x = fmaxf(acc[i][4], 0.f); o1.y = fmaxf(acc[i][5], 0.f);
            o1.z = fmaxf(acc[i][6], 0.f); o1.w = fmaxf(acc[i][7], 0.f);
            *(float4*)(out + (size_t)grow * H + (tx << 3))     = o0;
            *(float4*)(out + (size_t)grow * H + (tx << 3) + 4) = o1;
        }
    }
}

__global__ void gemm_ln_kernel(const float* __restrict__ A, const float* __restrict__ W,
                               const float* __restrict__ emb,
                               const float* __restrict__ ng, const float* __restrict__ nb,
                               float* __restrict__ out, int nrows) {
    extern __shared__ float smem[];
    float* sA = smem;
    float* sW = smem + H * GPITCH;
    float acc[8][8];
#pragma unroll
    for (int i = 0; i < 8; ++i)
#pragma unroll
        for (int j = 0; j < 8; ++j) acc[i][j] = 0.f;

    int row0 = blockIdx.x * 128;
    gemm_mainloop(A, nrows, row0, W, sA, sW, acc);

    int tid = threadIdx.x, tx = tid & 15, ty = tid >> 4;
    int c0 = tx << 3;
    float4 g0 = *(const float4*)(ng + c0);
    float4 g1 = *(const float4*)(ng + c0 + 4);
    float4 bb0 = *(const float4*)(nb + c0);
    float4 bb1 = *(const float4*)(nb + c0 + 4);
    float gv[8] = {g0.x, g0.y, g0.z, g0.w, g1.x, g1.y, g1.z, g1.w};
    float bv[8] = {bb0.x, bb0.y, bb0.z, bb0.w, bb1.x, bb1.y, bb1.z, bb1.w};

#pragma unroll
    for (int i = 0; i < 8; ++i) {
        int grow = row0 + (ty << 3) + i;
        bool valid = (grow < nrows);
        float4 e0 = make_float4(0.f, 0.f, 0.f, 0.f), e1 = e0;
        if (valid) {
            e0 = *(const float4*)(emb + (size_t)grow * H + c0);
            e1 = *(const float4*)(emb + (size_t)grow * H + c0 + 4);
        }
        float ev[8] = {e0.x, e0.y, e0.z, e0.w, e1.x, e1.y, e1.z, e1.w};
        float h[8];
        float s = 0.f;
#pragma unroll
        for (int j = 0; j < 8; ++j) {
            h[j] = 0.3f * ev[j] + 0.7f * fmaxf(acc[i][j], 0.f);
            s += h[j];
        }
        float mu = red16(s) * (1.f / 128.f);
        float ss = 0.f;
#pragma unroll
        for (int j = 0; j < 8; ++j) {
            h[j] -= mu;
            ss += h[j] * h[j];
        }
        float var = red16(ss) * (1.f / 128.f);
        float rstd = rsqrtf(var + 1e-5f);
        if (valid) {
            float o[8];
#pragma unroll
            for (int j = 0; j < 8; ++j)
                o[j] = h[j] * rstd * gv[j] + bv[j] + ev[j];
            *(float4*)(out + (size_t)grow * H + c0)     = make_float4(o[0], o[1], o[2], o[3]);
            *(float4*)(out + (size_t)grow * H + c0 + 4) = make_float4(o[4], o[5], o[6], o[7]);
        }
    }
}

__global__ void gemm_clf_kernel(const float* __restrict__ A, const float* __restrict__ W,
                                const float* __restrict__ mlp_b,
                                const float* __restrict__ clf_W, const float* __restrict__ clf_b,
                                float* __restrict__ out, int nrows) {
    extern __shared__ float smem[];
    float* sA = smem;
    float* sW = smem + H * GPITCH;
    float acc[8][8];
#pragma unroll
    for (int i = 0; i < 8; ++i)
#pragma unroll
        for (int j = 0; j < 8; ++j) acc[i][j] = 0.f;

    int row0 = blockIdx.x * 128;
    gemm_mainloop(A, nrows, row0, W, sA, sW, acc);

    int tid = threadIdx.x, tx = tid & 15, ty = tid >> 4;
    int c0 = tx << 3;
    float4 mb0 = *(const float4*)(mlp_b + c0);
    float4 mb1 = *(const float4*)(mlp_b + c0 + 4);
    float bias[8] = {mb0.x, mb0.y, mb0.z, mb0.w, mb1.x, mb1.y, mb1.z, mb1.w};
    float4 w00 = *(const float4*)(clf_W + c0);
    float4 w01 = *(const float4*)(clf_W + c0 + 4);
    float4 w10 = *(const float4*)(clf_W + H + c0);
    float4 w11 = *(const float4*)(clf_W + H + c0 + 4);
    float cv0[8] = {w00.x, w00.y, w00.z, w00.w, w01.x, w01.y, w01.z, w01.w};
    float cv1[8] = {w10.x, w10.y, w10.z, w10.w, w11.x, w11.y, w11.z, w11.w};
    float cb0 = __ldg(clf_b), cb1 = __ldg(clf_b + 1);

#pragma unroll
    for (int i = 0; i < 8; ++i) {
        int grow = row0 + (ty << 3) + i;
        float p0 = 0.f, p1 = 0.f;
#pragma unroll
        for (int j = 0; j < 8; ++j) {
            float hv = fmaxf(acc[i][j] + bias[j], 0.f);
            p0 += hv * cv0[j];
            p1 += hv * cv1[j];
        }
        p0 = red16(p0);
        p1 = red16(p1);
        if (tx == 0 && grow < nrows) {
            out[(size_t)grow * 2 + 0] = p0 + cb0;
            out[(size_t)grow * 2 + 1] = p1 + cb1;
        }
    }
}

// ---------------------------------------------------------------------------
// Host launcher
// ---------------------------------------------------------------------------
static void build_csr(const int* row, const int* col, const float* val, int nnz,
                      int nrows, int* ptr, int* cur, int* scol, float* sval, int* bsum) {
    int nb = (nrows + 1023) / 1024;
    zero_int_kernel<<<(nrows + 255) / 256, 256>>>(ptr, nrows);
    hist_kernel<<<(nnz + 255) / 256, 256>>>(row, nnz, ptr);
    scan1_kernel<<<nb, 1024>>>(ptr, ptr, bsum, nrows);
    scan2_kernel<<<1, 64>>>(bsum, nb);
    scan3_kernel<<<nb, 1024>>>(ptr, cur, bsum, nrows, nnz);
    scatter_kernel<<<(nnz + 255) / 256, 256>>>(row, col, val, nnz, cur, scol, sval);
}

extern "C" void kernel_launch(void* const* d_in, const int* in_sizes, int n_in,
                              void* d_out, int out_size) {
    const int*   A_row  = (const int*)d_in[0];
    const int*   A_col  = (const int*)d_in[1];
    const float* A_val  = (const float*)d_in[2];
    const int*   X_row  = (const int*)d_in[3];
    const int*   X_col  = (const int*)d_in[4];
    const float* X_val  = (const float*)d_in[5];
    const float* emb_W  = (const float*)d_in[6];
    const float* lin1_W = (const float*)d_in[7];
    const float* lin2_W = (const float*)d_in[8];
    const float* norm_g = (const float*)d_in[9];
    const float* norm_b = (const float*)d_in[10];
    const float* mlp_W  = (const float*)d_in[11];
    const float* mlp_b  = (const float*)d_in[12];
    const float* clf_W  = (const float*)d_in[13];
    const float* clf_b  = (const float*)d_in[14];
    float* out = (float*)d_out;

    int E    = in_sizes[0];
    int NNZ  = in_sizes[3];
    int V    = in_sizes[6] / H;
    int NDOC = out_size / 2;

    float *b1, *b2, *dc;
    int *aptr, *acur, *acol, *xptr, *xcur, *xcol, *bsum;
    float *aval, *xval;
    cudaGetSymbolAddress((void**)&b1,   g_buf1);
    cudaGetSymbolAddress((void**)&b2,   g_buf2);
    cudaGetSymbolAddress((void**)&dc,   g_doc);
    cudaGetSymbolAddress((void**)&aptr, gA_ptr);
    cudaGetSymbolAddress((void**)&acur, gA_cur);
    cudaGetSymbolAddress((void**)&acol, gA_col);
    cudaGetSymbolAddress((void**)&aval, gA_val);
    cudaGetSymbolAddress((void**)&xptr, gX_ptr);
    cudaGetSymbolAddress((void**)&xcur, gX_cur);
    cudaGetSymbolAddress((void**)&xcol, gX_col);
    cudaGetSymbolAddress((void**)&xval, gX_val);
    cudaGetSymbolAddress((void**)&bsum, g_bsum);

    size_t smem = (size_t)2 * H * GPITCH * sizeof(float);
    cudaFuncSetAttribute(gemm_relu_kernel, cudaFuncAttributeMaxDynamicSharedMemorySize, (int)smem);
    cudaFuncSetAttribute(gemm_ln_kernel,   cudaFuncAttributeMaxDynamicSharedMemorySize, (int)smem);
    cudaFuncSetAttribute(gemm_clf_kernel,  cudaFuncAttributeMaxDynamicSharedMemorySize, (int)smem);

    // Build CSR for both sparse matrices (sorted by row)
    build_csr(A_row, A_col, A_val, E,   V,    aptr, acur, acol, aval, bsum);
    build_csr(X_row, X_col, X_val, NNZ, NDOC, xptr, xcur, xcol, xval, bsum + 64);

    int vblocks = (V + 127) / 128;
    int dblocks = (NDOC + 127) / 128;
    int spmmV_blocks = (V * 32 + 255) / 256;
    int spmmD_blocks = (NDOC * 32 + 255) / 256;

    // 1) Hx1 = A @ emb
    spmm_csr_kernel<<<spmmV_blocks, 256>>>(aptr, acol, aval, emb_W, b1, V);
    // 2) Hx1 = relu(Hx1 @ lin1^T)
    gemm_relu_kernel<<<vblocks, 256, smem>>>(b1, lin1_W, b2, V);
    // 3) Hx2 = A @ Hx1
    spmm_csr_kernel<<<spmmV_blocks, 256>>>(aptr, acol, aval, b2, b1, V);
    // 4) wordsum = LN(0.3*emb + 0.7*relu(Hx2 @ lin2^T))*g + b + emb
    gemm_ln_kernel<<<vblocks, 256, smem>>>(b1, lin2_W, emb_W, norm_g, norm_b, b2, V);
    // 5) doc = X @ wordsum  (wordsum already includes +emb → doc_H + doc_H0)
    spmm_csr_kernel<<<spmmD_blocks, 256>>>(xptr, xcol, xval, b2, dc, NDOC);
    // 6) logits = relu(doc @ mlp^T + mlp_b) @ clf^T + clf_b
    gemm_clf_kernel<<<dblocks, 256, smem>>>(dc, mlp_W, mlp_b, clf_W, clf_b, out, NDOC);
}

// round 3
// speedup vs baseline: 1.5901x; 1.0375x over previous
#include <cuda_runtime.h>

#define H 128
#define GPITCH 132
#define VMAX 50048
#define DMAX 20096
#define EMAX 1600512
#define FULLM 0xffffffffu

// ---------------- static scratch (no allocation allowed) -------------------
__device__ float g_buf1[(size_t)VMAX * H];
__device__ float g_buf2[(size_t)VMAX * H];
__device__ float g_doc [(size_t)DMAX * H];

__device__ int   gA_ptr[VMAX + 1];
__device__ int   gA_cur[VMAX + 1];
__device__ int   gA_col[EMAX];
__device__ float gA_val[EMAX];
__device__ int   gX_ptr[DMAX + 1];
__device__ int   gX_cur[DMAX + 1];
__device__ int   gX_col[EMAX];
__device__ float gX_val[EMAX];

// ---------------------------------------------------------------------------
// CSR build, fused over both matrices: zero -> hist -> scan -> scatter
// ---------------------------------------------------------------------------
__global__ void zero_dual_kernel(int* __restrict__ pA, int nA,
                                 int* __restrict__ pX, int nX) {
    int i = blockIdx.x * blockDim.x + threadIdx.x;
    if (i < nA) pA[i] = 0;
    if (i < nX) pX[i] = 0;
}

__global__ void hist_dual_kernel(const int* __restrict__ rowA, int nE, int* __restrict__ cntA,
                                 const int* __restrict__ rowX, int nZ, int* __restrict__ cntX) {
    int i = blockIdx.x * blockDim.x + threadIdx.x;
    if (i < nE) atomicAdd(cntA + __ldg(rowA + i), 1);
    if (i < nZ) atomicAdd(cntX + __ldg(rowX + i), 1);
}

// One block per matrix: sequential-tile exclusive scan (1024 threads/tile).
__global__ void scan_dual_kernel(int* __restrict__ ptrA, int* __restrict__ curA, int nA, int nnzA,
                                 int* __restrict__ ptrX, int* __restrict__ curX, int nX, int nnzX) {
    int* ptr; int* cur; int n; int nnz;
    if (blockIdx.x == 0) { ptr = ptrA; cur = curA; n = nA; nnz = nnzA; }
    else                 { ptr = ptrX; cur = curX; n = nX; nnz = nnzX; }

    __shared__ int wsum[32];
    __shared__ int stotal;
    __shared__ int carry;
    int lane = threadIdx.x & 31, wid = threadIdx.x >> 5;
    if (threadIdx.x == 0) carry = 0;
    __syncthreads();

    int nt = (n + 1023) >> 10;
    for (int t = 0; t < nt; ++t) {
        int i = (t << 10) + threadIdx.x;
        int v = (i < n) ? ptr[i] : 0;
        int x = v;
#pragma unroll
        for (int off = 1; off < 32; off <<= 1) {
            int y = __shfl_up_sync(FULLM, x, off);
            if (lane >= off) x += y;
        }
        if (lane == 31) wsum[wid] = x;
        __syncthreads();
        if (wid == 0) {
            int w = wsum[lane];
            int xx = w;
#pragma unroll
            for (int off = 1; off < 32; off <<= 1) {
                int y = __shfl_up_sync(FULLM, xx, off);
                if (lane >= off) xx += y;
            }
            wsum[lane] = xx - w;                 // exclusive warp offsets
            if (lane == 31) stotal = xx;         // tile total
        }
        __syncthreads();
        int excl = x - v + wsum[wid] + carry;
        if (i < n) { ptr[i] = excl; cur[i] = excl; }
        __syncthreads();                          // all reads of carry done
        if (threadIdx.x == 0) carry += stotal;
        __syncthreads();
    }
    if (threadIdx.x == 0) { ptr[n] = nnz; cur[n] = nnz; }
}

__global__ void scatter_dual_kernel(
        const int* __restrict__ rowA, const int* __restrict__ colA,
        const float* __restrict__ valA, int nE, int* __restrict__ curA,
        int* __restrict__ acol, float* __restrict__ aval,
        const int* __restrict__ rowX, const int* __restrict__ colX,
        const float* __restrict__ valX, int nZ, int* __restrict__ curX,
        int* __restrict__ xcol, float* __restrict__ xval) {
    int i = blockIdx.x * blockDim.x + threadIdx.x;
    if (i < nE) {
        int r = __ldg(rowA + i);
        int p = atomicAdd(curA + r, 1);
        acol[p] = __ldg(colA + i);
        aval[p] = __ldg(valA + i);
    }
    if (i < nZ) {
        int r = __ldg(rowX + i);
        int p = atomicAdd(curX + r, 1);
        xcol[p] = __ldg(colX + i);
        xval[p] = __ldg(valX + i);
    }
}

// ---------------------------------------------------------------------------
// Gather SpMM over CSR: one warp per output row, float4 accumulator per lane.
// Full 32-edge chunks take a branch-free unrolled path.
// ---------------------------------------------------------------------------
__global__ void spmm_csr_kernel(const int* __restrict__ ptr, const int* __restrict__ cols,
                                const float* __restrict__ vals, const float* __restrict__ src,
                                float* __restrict__ dst, int nrows) {
    int w = (blockIdx.x * blockDim.x + threadIdx.x) >> 5;
    if (w >= nrows) return;
    int lane = threadIdx.x & 31;
    int beg = __ldg(ptr + w);
    int end = __ldg(ptr + w + 1);
    float4 acc = make_float4(0.f, 0.f, 0.f, 0.f);

    int base = beg;
    for (; base + 32 <= end; base += 32) {
        int   c = __ldg(cols + base + lane);
        float v = __ldg(vals + base + lane);
#pragma unroll 8
        for (int j = 0; j < 32; ++j) {
            int   cj = __shfl_sync(FULLM, c, j);
            float vj = __shfl_sync(FULLM, v, j);
            float4 s = ((const float4*)(src + (size_t)cj * H))[lane];
            acc.x += vj * s.x; acc.y += vj * s.y; acc.z += vj * s.z; acc.w += vj * s.w;
        }
    }
    if (base < end) {
        int n = end - base;
        int c = 0; float v = 0.f;
        if (base + lane < end) {
            c = __ldg(cols + base + lane);
            v = __ldg(vals + base + lane);
        }
        int j = 0;
        for (; j + 4 <= n; j += 4) {
            int   c0 = __shfl_sync(FULLM, c, j + 0);
            int   c1 = __shfl_sync(FULLM, c, j + 1);
            int   c2 = __shfl_sync(FULLM, c, j + 2);
            int   c3 = __shfl_sync(FULLM, c, j + 3);
            float v0 = __shfl_sync(FULLM, v, j + 0);
            float v1 = __shfl_sync(FULLM, v, j + 1);
            float v2 = __shfl_sync(FULLM, v, j + 2);
            float v3 = __shfl_sync(FULLM, v, j + 3);
            float4 s0 = ((const float4*)(src + (size_t)c0 * H))[lane];
            float4 s1 = ((const float4*)(src + (size_t)c1 * H))[lane];
            float4 s2 = ((const float4*)(src + (size_t)c2 * H))[lane];
            float4 s3 = ((const float4*)(src + (size_t)c3 * H))[lane];
            acc.x += v0 * s0.x; acc.y += v0 * s0.y; acc.z += v0 * s0.z; acc.w += v0 * s0.w;
            acc.x += v1 * s1.x; acc.y += v1 * s1.y; acc.z += v1 * s1.z; acc.w += v1 * s1.w;
            acc.x += v2 * s2.x; acc.y += v2 * s2.y; acc.z += v2 * s2.z; acc.w += v2 * s2.w;
            acc.x += v3 * s3.x; acc.y += v3 * s3.y; acc.z += v3 * s3.z; acc.w += v3 * s3.w;
        }
        for (; j < n; ++j) {
            int   cj = __shfl_sync(FULLM, c, j);
            float vj = __shfl_sync(FULLM, v, j);
            float4 s = ((const float4*)(src + (size_t)cj * H))[lane];
            acc.x += vj * s.x; acc.y += vj * s.y; acc.z += vj * s.z; acc.w += vj * s.w;
        }
    }
    ((float4*)(dst + (size_t)w * H))[lane] = acc;
}

// ---------------------------------------------------------------------------
// GEMM mainloop: 128x128 tile, 256 thr, 8x8 micro-tiles
// ---------------------------------------------------------------------------
__device__ __forceinline__ void gemm_mainloop(const float* __restrict__ A, int nrows, int row0,
                                              const float* __restrict__ W,
                                              float* sA, float* sW,
                                              float acc[8][8]) {
    int tid = threadIdx.x;
#pragma unroll
    for (int it = 0; it < 16; ++it) {
        int idx = it * 256 + tid;
        int r   = idx & 127;
        int k4  = idx >> 7;
        int grow = row0 + r;
        float4 a = make_float4(0.f, 0.f, 0.f, 0.f);
        if (grow < nrows) a = *(const float4*)(A + (size_t)grow * H + k4 * 4);
        sA[(4 * k4 + 0) * GPITCH + r] = a.x;
        sA[(4 * k4 + 1) * GPITCH + r] = a.y;
        sA[(4 * k4 + 2) * GPITCH + r] = a.z;
        sA[(4 * k4 + 3) * GPITCH + r] = a.w;
        float4 wv = *(const float4*)(W + (size_t)r * H + k4 * 4);
        sW[(4 * k4 + 0) * GPITCH + r] = wv.x;
        sW[(4 * k4 + 1) * GPITCH + r] = wv.y;
        sW[(4 * k4 + 2) * GPITCH + r] = wv.z;
        sW[(4 * k4 + 3) * GPITCH + r] = wv.w;
    }
    __syncthreads();

    int tx = tid & 15, ty = tid >> 4;
#pragma unroll 4
    for (int k = 0; k < H; ++k) {
        const float* pa = sA + k * GPITCH + (ty << 3);
        const float* pb = sW + k * GPITCH + (tx << 3);
        float4 a0 = *(const float4*)(pa);
        float4 a1 = *(const float4*)(pa + 4);
        float4 b0 = *(const float4*)(pb);
        float4 b1 = *(const float4*)(pb + 4);
        float av[8] = {a0.x, a0.y, a0.z, a0.w, a1.x, a1.y, a1.z, a1.w};
        float bv[8] = {b0.x, b0.y, b0.z, b0.w, b1.x, b1.y, b1.z, b1.w};
#pragma unroll
        for (int i = 0; i < 8; ++i)
#pragma unroll
            for (int j = 0; j < 8; ++j)
                acc[i][j] += av[i] * bv[j];
    }
}

__device__ __forceinline__ float red16(float v) {
#pragma unroll
    for (int off = 8; off > 0; off >>= 1)
        v += __shfl_xor_sync(FULLM, v, off, 16);
    return v;
}

__global__ void gemm_relu_kernel(const float* __restrict__ A, const float* __restrict__ W,
                                 float* __restrict__ out, int nrows) {
    extern __shared__ float smem[];
    float* sA = smem;
    float* sW = smem + H * GPITCH;
    float acc[8][8];
#pragma unroll
    for (int i = 0; i < 8; ++i)
#pragma unroll
        for (int j = 0; j < 8; ++j) acc[i][j] = 0.f;

    int row0 = blockIdx.x * 128;
    gemm_mainloop(A, nrows, row0, W, sA, sW, acc);

    int tid = threadIdx.x, tx = tid & 15, ty = tid >> 4;
#pragma unroll
    for (int i = 0; i < 8; ++i) {
        int grow = row0 + (ty << 3) + i;
        if (grow < nrows) {
            float4 o0, o1;
            o0.x = fmaxf(acc[i][0], 0.f); o0.y = fmaxf(acc[i][1], 0.f);
            o0.z = fmaxf(acc[i][2], 0.f); o0.w = fmaxf(acc[i][3], 0.f);
            o1.x = fmaxf(acc[i][4], 0.f); o1.y = fmaxf(acc[i][5], 0.f);
            o1.z = fmaxf(acc[i][6], 0.f); o1.w = fmaxf(acc[i][7], 0.f);
            *(float4*)(out + (size_t)grow * H + (tx << 3))     = o0;
            *(float4*)(out + (size_t)grow * H + (tx << 3) + 4) = o1;
        }
    }
}

__global__ void gemm_ln_kernel(const float* __restrict__ A, const float* __restrict__ W,
                               const float* __restrict__ emb,
                               const float* __restrict__ ng, const float* __restrict__ nb,
                               float* __restrict__ out, int nrows) {
    extern __shared__ float smem[];
    float* sA = smem;
    float* sW = smem + H * GPITCH;
    float acc[8][8];
#pragma unroll
    for (int i = 0; i < 8; ++i)
#pragma unroll
        for (int j = 0; j < 8; ++j) acc[i][j] = 0.f;

    int row0 = blockIdx.x * 128;
    gemm_mainloop(A, nrows, row0, W, sA, sW, acc);

    int tid = threadIdx.x, tx = tid & 15, ty = tid >> 4;
    int c0 = tx << 3;
    float4 g0 = *(const float4*)(ng + c0);
    float4 g1 = *(const float4*)(ng + c0 + 4);
    float4 bb0 = *(const float4*)(nb + c0);
    float4 bb1 = *(const float4*)(nb + c0 + 4);
    float gv[8] = {g0.x, g0.y, g0.z, g0.w, g1.x, g1.y, g1.z, g1.w};
    float bv[8] = {bb0.x, bb0.y, bb0.z, bb0.w, bb1.x, bb1.y, bb1.z, bb1.w};

#pragma unroll
    for (int i = 0; i < 8; ++i) {
        int grow = row0 + (ty << 3) + i;
        bool valid = (grow < nrows);
        float4 e0 = make_float4(0.f, 0.f, 0.f, 0.f), e1 = e0;
        if (valid) {
            e0 = *(const float4*)(emb + (size_t)grow * H + c0);
            e1 = *(const float4*)(emb + (size_t)grow * H + c0 + 4);
        }
        float ev[8] = {e0.x, e0.y, e0.z, e0.w, e1.x, e1.y, e1.z, e1.w};
        float h[8];
        float s = 0.f;
#pragma unroll
        for (int j = 0; j < 8; ++j) {
            h[j] = 0.3f * ev[j] + 0.7f * fmaxf(acc[i][j], 0.f);
            s += h[j];
        }
        float mu = red16(s) * (1.f / 128.f);
        float ss = 0.f;
#pragma unroll
        for (int j = 0; j < 8; ++j) {
            h[j] -= mu;
            ss += h[j] * h[j];
        }
        float var = red16(ss) * (1.f / 128.f);
        float rstd = rsqrtf(var + 1e-5f);
        if (valid) {
            float o[8];
#pragma unroll
            for (int j = 0; j < 8; ++j)
                o[j] = h[j] * rstd * gv[j] + bv[j] + ev[j];
            *(float4*)(out + (size_t)grow * H + c0)     = make_float4(o[0], o[1], o[2], o[3]);
            *(float4*)(out + (size_t)grow * H + c0 + 4) = make_float4(o[4], o[5], o[6], o[7]);
        }
    }
}

__global__ void gemm_clf_kernel(const float* __restrict__ A, const float* __restrict__ W,
                                const float* __restrict__ mlp_b,
                                const float* __restrict__ clf_W, const float* __restrict__ clf_b,
                                float* __restrict__ out, int nrows) {
    extern __shared__ float smem[];
    float* sA = smem;
    float* sW = smem + H * GPITCH;
    float acc[8][8];
#pragma unroll
    for (int i = 0; i < 8; ++i)
#pragma unroll
        for (int j = 0; j < 8; ++j) acc[i][j] = 0.f;

    int row0 = blockIdx.x * 128;
    gemm_mainloop(A, nrows, row0, W, sA, sW, acc);

    int tid = threadIdx.x, tx = tid & 15, ty = tid >> 4;
    int c0 = tx << 3;
    float4 mb0 = *(const float4*)(mlp_b + c0);
    float4 mb1 = *(const float4*)(mlp_b + c0 + 4);
    float bias[8] = {mb0.x, mb0.y, mb0.z, mb0.w, mb1.x, mb1.y, mb1.z, mb1.w};
    float4 w00 = *(const float4*)(clf_W + c0);
    float4 w01 = *(const float4*)(clf_W + c0 + 4);
    float4 w10 = *(const float4*)(clf_W + H + c0);
    float4 w11 = *(const float4*)(clf_W + H + c0 + 4);
    float cv0[8] = {w00.x, w00.y, w00.z, w00.w, w01.x, w01.y, w01.z, w01.w};
    float cv1[8] = {w10.x, w10.y, w10.z, w10.w, w11.x, w11.y, w11.z, w11.w};
    float cb0 = __ldg(clf_b), cb1 = __ldg(clf_b + 1);

#pragma unroll
    for (int i = 0; i < 8; ++i) {
        int grow = row0 + (ty << 3) + i;
        float p0 = 0.f, p1 = 0.f;
#pragma unroll
        for (int j = 0; j < 8; ++j) {
            float hv = fmaxf(acc[i][j] + bias[j], 0.f);
            p0 += hv * cv0[j];
            p1 += hv * cv1[j];
        }
        p0 = red16(p0);
        p1 = red16(p1);
        if (tx == 0 && grow < nrows) {
            out[(size_t)grow * 2 + 0] = p0 + cb0;
            out[(size_t)grow * 2 + 1] = p1 + cb1;
        }
    }
}

// ---------------------------------------------------------------------------
// Host launcher
// ---------------------------------------------------------------------------
extern "C" void kernel_launch(void* const* d_in, const int* in_sizes, int n_in,
                              void* d_out, int out_size) {
    const int*   A_row  = (const int*)d_in[0];
    const int*   A_col  = (const int*)d_in[1];
    const float* A_val  = (const float*)d_in[2];
    const int*   X_row  = (const int*)d_in[3];
    const int*   X_col  = (const int*)d_in[4];
    const float* X_val  = (const float*)d_in[5];
    const float* emb_W  = (const float*)d_in[6];
    const float* lin1_W = (const float*)d_in[7];
    const float* lin2_W = (const float*)d_in[8];
    const float* norm_g = (const float*)d_in[9];
    const float* norm_b = (const float*)d_in[10];
    const float* mlp_W  = (const float*)d_in[11];
    const float* mlp_b  = (const float*)d_in[12];
    const float* clf_W  = (const float*)d_in[13];
    const float* clf_b  = (const float*)d_in[14];
    float* out = (float*)d_out;

    int E    = in_sizes[0];
    int NNZ  = in_sizes[3];
    int V    = in_sizes[6] / H;
    int NDOC = out_size / 2;

    float *b1, *b2, *dc;
    int *aptr, *acur, *acol, *xptr, *xcur, *xcol;
    float *aval, *xval;
    cudaGetSymbolAddress((void**)&b1,   g_buf1);
    cudaGetSymbolAddress((void**)&b2,   g_buf2);
    cudaGetSymbolAddress((void**)&dc,   g_doc);
    cudaGetSymbolAddress((void**)&aptr, gA_ptr);
    cudaGetSymbolAddress((void**)&acur, gA_cur);
    cudaGetSymbolAddress((void**)&acol, gA_col);
    cudaGetSymbolAddress((void**)&aval, gA_val);
    cudaGetSymbolAddress((void**)&xptr, gX_ptr);
    cudaGetSymbolAddress((void**)&xcur, gX_cur);
    cudaGetSymbolAddress((void**)&xcol, gX_col);
    cudaGetSymbolAddress((void**)&xval, gX_val);

    size_t smem = (size_t)2 * H * GPITCH * sizeof(float);
    cudaFuncSetAttribute(gemm_relu_kernel, cudaFuncAttributeMaxDynamicSharedMemorySize, (int)smem);
    cudaFuncSetAttribute(gemm_ln_kernel,   cudaFuncAttributeMaxDynamicSharedMemorySize, (int)smem);
    cudaFuncSetAttribute(gemm_clf_kernel,  cudaFuncAttributeMaxDynamicSharedMemorySize, (int)smem);

    // --- CSR build for both matrices: 4 launches total ---
    int zmax = (V > NDOC ? V : NDOC) + 1;
    int emax = (E > NNZ ? E : NNZ);
    zero_dual_kernel<<<(zmax + 255) / 256, 256>>>(aptr, V, xptr, NDOC);
    hist_dual_kernel<<<(emax + 255) / 256, 256>>>(A_row, E, aptr, X_row, NNZ, xptr);
    scan_dual_kernel<<<2, 1024>>>(aptr, acur, V, E, xptr, xcur, NDOC, NNZ);
    scatter_dual_kernel<<<(emax + 255) / 256, 256>>>(A_row, A_col, A_val, E, acur, acol, aval,
                                                     X_row, X_col, X_val, NNZ, xcur, xcol, xval);

    int vblocks = (V + 127) / 128;
    int dblocks = (NDOC + 127) / 128;
    int spmmV_blocks = (V * 32 + 255) / 256;
    int spmmD_blocks = (NDOC * 32 + 255) / 256;

    // 1) Hx1 = A @ emb
    spmm_csr_kernel<<<spmmV_blocks, 256>>>(aptr, acol, aval, emb_W, b1, V);
    // 2) Hx1 = relu(Hx1 @ lin1^T)
    gemm_relu_kernel<<<vblocks, 256, smem>>>(b1, lin1_W, b2, V);
    // 3) Hx2 = A @ Hx1
    spmm_csr_kernel<<<spmmV_blocks, 256>>>(aptr, acol, aval, b2, b1, V);
    // 4) wordsum = LN(0.3*emb + 0.7*relu(Hx2 @ lin2^T))*g + b + emb
    gemm_ln_kernel<<<vblocks, 256, smem>>>(b1, lin2_W, emb_W, norm_g, norm_b, b2, V);
    // 5) doc = X @ wordsum  (wordsum already includes +emb)
    spmm_csr_kernel<<<spmmD_blocks, 256>>>(xptr, xcol, xval, b2, dc, NDOC);
    // 6) logits = relu(doc @ mlp^T + mlp_b) @ clf^T + clf_b
    gemm_clf_kernel<<<dblocks, 256, smem>>>(dc, mlp_W, mlp_b, clf_W, clf_b, out, NDOC);
}

// round 9
// speedup vs baseline: 1.8131x; 1.1402x over previous
#include <cuda_runtime.h>
#include <cuda_fp16.h>

#define H 128
#define GPITCH 132
#define VMAX 50048
#define DMAX 20096
#define EMAX 1600512
#define FULLM 0xffffffffu

// ---------------- static scratch (no allocation allowed) -------------------
__device__ float  g_buf1[(size_t)VMAX * H];    // fp32 SpMM outputs
__device__ float  g_doc [(size_t)DMAX * H];
__device__ __half g_h1  [(size_t)VMAX * H];    // half SpMM sources
__device__ __half g_h2  [(size_t)VMAX * H];

__device__ int  gA_ptr[VMAX + 1];
__device__ int  gA_cur[VMAX + 1];
__device__ int2 gA_cv[EMAX];                   // interleaved {col, val_bits}
__device__ int  gX_ptr[DMAX + 1];
__device__ int  gX_cur[DMAX + 1];
__device__ int2 gX_cv[EMAX];

// ---------------------------------------------------------------------------
// CSR build: zero -> hist -> scan -> scatter (both matrices per kernel)
// ---------------------------------------------------------------------------
__global__ void zero_dual_kernel(int* __restrict__ pA, int nA,
                                 int* __restrict__ pX, int nX) {
    int i = blockIdx.x * blockDim.x + threadIdx.x;
    if (i < nA) pA[i] = 0;
    if (i < nX) pX[i] = 0;
}

__global__ void hist_dual_kernel(const int* __restrict__ rowA, int nE, int* __restrict__ cntA,
                                 const int* __restrict__ rowX, int nZ, int* __restrict__ cntX) {
    int i = blockIdx.x * blockDim.x + threadIdx.x;
    if (i < nE) atomicAdd(cntA + __ldg(rowA + i), 1);
    if (i < nZ) atomicAdd(cntX + __ldg(rowX + i), 1);
}

// One block per matrix: sequential-tile exclusive scan (1024 threads/tile).
__global__ void scan_dual_kernel(int* __restrict__ ptrA, int* __restrict__ curA, int nA, int nnzA,
                                 int* __restrict__ ptrX, int* __restrict__ curX, int nX, int nnzX) {
    int* ptr; int* cur; int n; int nnz;
    if (blockIdx.x == 0) { ptr = ptrA; cur = curA; n = nA; nnz = nnzA; }
    else                 { ptr = ptrX; cur = curX; n = nX; nnz = nnzX; }

    __shared__ int wsum[32];
    __shared__ int stotal;
    __shared__ int carry;
    int lane = threadIdx.x & 31, wid = threadIdx.x >> 5;
    if (threadIdx.x == 0) carry = 0;
    __syncthreads();

    int nt = (n + 1023) >> 10;
    for (int t = 0; t < nt; ++t) {
        int i = (t << 10) + threadIdx.x;
        int v = (i < n) ? ptr[i] : 0;
        int x = v;
#pragma unroll
        for (int off = 1; off < 32; off <<= 1) {
            int y = __shfl_up_sync(FULLM, x, off);
            if (lane >= off) x += y;
        }
        if (lane == 31) wsum[wid] = x;
        __syncthreads();
        if (wid == 0) {
            int w = wsum[lane];
            int xx = w;
#pragma unroll
            for (int off = 1; off < 32; off <<= 1) {
                int y = __shfl_up_sync(FULLM, xx, off);
                if (lane >= off) xx += y;
            }
            wsum[lane] = xx - w;
            if (lane == 31) stotal = xx;
        }
        __syncthreads();
        int excl = x - v + wsum[wid] + carry;
        if (i < n) { ptr[i] = excl; cur[i] = excl; }
        __syncthreads();
        if (threadIdx.x == 0) carry += stotal;
        __syncthreads();
    }
    if (threadIdx.x == 0) { ptr[n] = nnz; cur[n] = nnz; }
}

__global__ void scatter_dual_kernel(
        const int* __restrict__ rowA, const int* __restrict__ colA,
        const float* __restrict__ valA, int nE, int* __restrict__ curA,
        int2* __restrict__ acv,
        const int* __restrict__ rowX, const int* __restrict__ colX,
        const float* __restrict__ valX, int nZ, int* __restrict__ curX,
        int2* __restrict__ xcv) {
    int i = blockIdx.x * blockDim.x + threadIdx.x;
    if (i < nE) {
        int r = __ldg(rowA + i);
        int p = atomicAdd(curA + r, 1);
        acv[p] = make_int2(__ldg(colA + i), __float_as_int(__ldg(valA + i)));
    }
    if (i < nZ) {
        int r = __ldg(rowX + i);
        int p = atomicAdd(curX + r, 1);
        xcv[p] = make_int2(__ldg(colX + i), __float_as_int(__ldg(valX + i)));
    }
}

// fp32 -> fp16 convert (float4 -> 4 halves)
__global__ void f2h_kernel(const float* __restrict__ src, __half* __restrict__ dst, int n4) {
    int i = blockIdx.x * blockDim.x + threadIdx.x;
    for (; i < n4; i += gridDim.x * blockDim.x) {
        float4 f = ((const float4*)src)[i];
        __half2 h0 = __floats2half2_rn(f.x, f.y);
        __half2 h1 = __floats2half2_rn(f.z, f.w);
        uint2 u;
        u.x = *(unsigned*)&h0;
        u.y = *(unsigned*)&h1;
        ((uint2*)dst)[i] = u;
    }
}

// ---------------------------------------------------------------------------
// Gather SpMM over CSR (half source, fp32 accumulate):
// one warp per row, lane handles 4 columns (8B half gather -> float4 acc)
// ---------------------------------------------------------------------------
__device__ __forceinline__ void spmm_edge(float4& acc, const __half* __restrict__ src,
                                          int c, float v, int lane) {
    uint2 u = __ldg(((const uint2*)(src + (size_t)c * H)) + lane);
    __half2 h0 = *(__half2*)&u.x;
    __half2 h1 = *(__half2*)&u.y;
    float2 f0 = __half22float2(h0);
    float2 f1 = __half22float2(h1);
    acc.x += v * f0.x; acc.y += v * f0.y;
    acc.z += v * f1.x; acc.w += v * f1.y;
}

__global__ void spmm_csr_kernel(const int* __restrict__ ptr, const int2* __restrict__ cv,
                                const __half* __restrict__ src,
                                float* __restrict__ dst, int nrows) {
    int w = (blockIdx.x * blockDim.x + threadIdx.x) >> 5;
    if (w >= nrows) return;
    int lane = threadIdx.x & 31;
    int beg = __ldg(ptr + w);
    int end = __ldg(ptr + w + 1);
    float4 acc = make_float4(0.f, 0.f, 0.f, 0.f);

    int base = beg;
    for (; base + 32 <= end; base += 32) {
        int2 e = __ldg(cv + base + lane);
        int c = e.x;
        float v = __int_as_float(e.y);
#pragma unroll 8
        for (int j = 0; j < 32; ++j) {
            int   cj = __shfl_sync(FULLM, c, j);
            float vj = __shfl_sync(FULLM, v, j);
            spmm_edge(acc, src, cj, vj, lane);
        }
    }
    if (base < end) {
        int n = end - base;
        int c = 0; float v = 0.f;
        if (base + lane < end) {
            int2 e = __ldg(cv + base + lane);
            c = e.x;
            v = __int_as_float(e.y);
        }
        int j = 0;
        for (; j + 4 <= n; j += 4) {
#pragma unroll
            for (int q = 0; q < 4; ++q) {
                int   cj = __shfl_sync(FULLM, c, j + q);
                float vj = __shfl_sync(FULLM, v, j + q);
                spmm_edge(acc, src, cj, vj, lane);
            }
        }
        for (; j < n; ++j) {
            int   cj = __shfl_sync(FULLM, c, j);
            float vj = __shfl_sync(FULLM, v, j);
            spmm_edge(acc, src, cj, vj, lane);
        }
    }
    ((float4*)(dst + (size_t)w * H))[lane] = acc;
}

// ---------------------------------------------------------------------------
// GEMM mainloop: 128x128 tile, 256 thr, 8x8 micro-tiles (fp32 in)
// ---------------------------------------------------------------------------
__device__ __forceinline__ void gemm_mainloop(const float* __restrict__ A, int nrows, int row0,
                                              const float* __restrict__ W,
                                              float* sA, float* sW,
                                              float acc[8][8]) {
    int tid = threadIdx.x;
#pragma unroll
    for (int it = 0; it < 16; ++it) {
        int idx = it * 256 + tid;
        int r   = idx & 127;
        int k4  = idx >> 7;
        int grow = row0 + r;
        float4 a = make_float4(0.f, 0.f, 0.f, 0.f);
        if (grow < nrows) a = *(const float4*)(A + (size_t)grow * H + k4 * 4);
        sA[(4 * k4 + 0) * GPITCH + r] = a.x;
        sA[(4 * k4 + 1) * GPITCH + r] = a.y;
        sA[(4 * k4 + 2) * GPITCH + r] = a.z;
        sA[(4 * k4 + 3) * GPITCH + r] = a.w;
        float4 wv = *(const float4*)(W + (size_t)r * H + k4 * 4);
        sW[(4 * k4 + 0) * GPITCH + r] = wv.x;
        sW[(4 * k4 + 1) * GPITCH + r] = wv.y;
        sW[(4 * k4 + 2) * GPITCH + r] = wv.z;
        sW[(4 * k4 + 3) * GPITCH + r] = wv.w;
    }
    __syncthreads();

    int tx = tid & 15, ty = tid >> 4;
#pragma unroll 4
    for (int k = 0; k < H; ++k) {
        const float* pa = sA + k * GPITCH + (ty << 3);
        const float* pb = sW + k * GPITCH + (tx << 3);
        float4 a0 = *(const float4*)(pa);
        float4 a1 = *(const float4*)(pa + 4);
        float4 b0 = *(const float4*)(pb);
        float4 b1 = *(const float4*)(pb + 4);
        float av[8] = {a0.x, a0.y, a0.z, a0.w, a1.x, a1.y, a1.z, a1.w};
        float bv[8] = {b0.x, b0.y, b0.z, b0.w, b1.x, b1.y, b1.z, b1.w};
#pragma unroll
        for (int i = 0; i < 8; ++i)
#pragma unroll
            for (int j = 0; j < 8; ++j)
                acc[i][j] += av[i] * bv[j];
    }
}

__device__ __forceinline__ float red16(float v) {
#pragma unroll
    for (int off = 8; off > 0; off >>= 1)
        v += __shfl_xor_sync(FULLM, v, off, 16);
    return v;
}

// pack 8 floats -> 8 halves (16B) and store
__device__ __forceinline__ void store_half8(__half* dst, const float* o) {
    __half2 h0 = __floats2half2_rn(o[0], o[1]);
    __half2 h1 = __floats2half2_rn(o[2], o[3]);
    __half2 h2 = __floats2half2_rn(o[4], o[5]);
    __half2 h3 = __floats2half2_rn(o[6], o[7]);
    uint4 u;
    u.x = *(unsigned*)&h0; u.y = *(unsigned*)&h1;
    u.z = *(unsigned*)&h2; u.w = *(unsigned*)&h3;
    *(uint4*)dst = u;
}

// out_h = half(relu(A @ W^T))
__global__ void gemm_relu_kernel(const float* __restrict__ A, const float* __restrict__ W,
                                 __half* __restrict__ out, int nrows) {
    extern __shared__ float smem[];
    float* sA = smem;
    float* sW = smem + H * GPITCH;
    float acc[8][8];
#pragma unroll
    for (int i = 0; i < 8; ++i)
#pragma unroll
        for (int j = 0; j < 8; ++j) acc[i][j] = 0.f;

    int row0 = blockIdx.x * 128;
    gemm_mainloop(A, nrows, row0, W, sA, sW, acc);

    int tid = threadIdx.x, tx = tid & 15, ty = tid >> 4;
#pragma unroll
    for (int i = 0; i < 8; ++i) {
        int grow = row0 + (ty << 3) + i;
        if (grow < nrows) {
            float o[8];
#pragma unroll
            for (int j = 0; j < 8; ++j) o[j] = fmaxf(acc[i][j], 0.f);
            store_half8(out + (size_t)grow * H + (tx << 3), o);
        }
    }
}

// out_h = half( LN(0.3*emb + 0.7*relu(A @ W^T))*g + b + emb )
__global__ void gemm_ln_kernel(const float* __restrict__ A, const float* __restrict__ W,
                               const float* __restrict__ emb,
                               const float* __restrict__ ng, const float* __restrict__ nb,
                               __half* __restrict__ out, int nrows) {
    extern __shared__ float smem[];
    float* sA = smem;
    float* sW = smem + H * GPITCH;
    float acc[8][8];
#pragma unroll
    for (int i = 0; i < 8; ++i)
#pragma unroll
        for (int j = 0; j < 8; ++j) acc[i][j] = 0.f;

    int row0 = blockIdx.x * 128;
    gemm_mainloop(A, nrows, row0, W, sA, sW, acc);

    int tid = threadIdx.x, tx = tid & 15, ty = tid >> 4;
    int c0 = tx << 3;
    float4 g0 = *(const float4*)(ng + c0);
    float4 g1 = *(const float4*)(ng + c0 + 4);
    float4 bb0 = *(const float4*)(nb + c0);
    float4 bb1 = *(const float4*)(nb + c0 + 4);
    float gv[8] = {g0.x, g0.y, g0.z, g0.w, g1.x, g1.y, g1.z, g1.w};
    float bv[8] = {bb0.x, bb0.y, bb0.z, bb0.w, bb1.x, bb1.y, bb1.z, bb1.w};

#pragma unroll
    for (int i = 0; i < 8; ++i) {
        int grow = row0 + (ty << 3) + i;
        bool valid = (grow < nrows);
        float4 e0 = make_float4(0.f, 0.f, 0.f, 0.f), e1 = e0;
        if (valid) {
            e0 = *(const float4*)(emb + (size_t)grow * H + c0);
            e1 = *(const float4*)(emb + (size_t)grow * H + c0 + 4);
        }
        float ev[8] = {e0.x, e0.y, e0.z, e0.w, e1.x, e1.y, e1.z, e1.w};
        float h[8];
        float s = 0.f;
#pragma unroll
        for (int j = 0; j < 8; ++j) {
            h[j] = 0.3f * ev[j] + 0.7f * fmaxf(acc[i][j], 0.f);
            s += h[j];
        }
        float mu = red16(s) * (1.f / 128.f);
        float ss = 0.f;
#pragma unroll
        for (int j = 0; j < 8; ++j) {
            h[j] -= mu;
            ss += h[j] * h[j];
        }
        float var = red16(ss) * (1.f / 128.f);
        float rstd = rsqrtf(var + 1e-5f);
        if (valid) {
            float o[8];
#pragma unroll
            for (int j = 0; j < 8; ++j)
                o[j] = h[j] * rstd * gv[j] + bv[j] + ev[j];
            store_half8(out + (size_t)grow * H + c0, o);
        }
    }
}

// logits = relu(A @ mlpW^T + mlp_b) @ clfW^T + clf_b
__global__ void gemm_clf_kernel(const float* __restrict__ A, const float* __restrict__ W,
                                const float* __restrict__ mlp_b,
                                const float* __restrict__ clf_W, const float* __restrict__ clf_b,
                                float* __restrict__ out, int nrows) {
    extern __shared__ float smem[];
    float* sA = smem;
    float* sW = smem + H * GPITCH;
    float acc[8][8];
#pragma unroll
    for (int i = 0; i < 8; ++i)
#pragma unroll
        for (int j = 0; j < 8; ++j) acc[i][j] = 0.f;

    int row0 = blockIdx.x * 128;
    gemm_mainloop(A, nrows, row0, W, sA, sW, acc);

    int tid = threadIdx.x, tx = tid & 15, ty = tid >> 4;
    int c0 = tx << 3;
    float4 mb0 = *(const float4*)(mlp_b + c0);
    float4 mb1 = *(const float4*)(mlp_b + c0 + 4);
    float bias[8] = {mb0.x, mb0.y, mb0.z, mb0.w, mb1.x, mb1.y, mb1.z, mb1.w};
    float4 w00 = *(const float4*)(clf_W + c0);
    float4 w01 = *(const float4*)(clf_W + c0 + 4);
    float4 w10 = *(const float4*)(clf_W + H + c0);
    float4 w11 = *(const float4*)(clf_W + H + c0 + 4);
    float cv0[8] = {w00.x, w00.y, w00.z, w00.w, w01.x, w01.y, w01.z, w01.w};
    float cv1[8] = {w10.x, w10.y, w10.z, w10.w, w11.x, w11.y, w11.z, w11.w};
    float cb0 = __ldg(clf_b), cb1 = __ldg(clf_b + 1);

#pragma unroll
    for (int i = 0; i < 8; ++i) {
        int grow = row0 + (ty << 3) + i;
        float p0 = 0.f, p1 = 0.f;
#pragma unroll
        for (int j = 0; j < 8; ++j) {
            float hv = fmaxf(acc[i][j] + bias[j], 0.f);
            p0 += hv * cv0[j];
            p1 += hv * cv1[j];
        }
        p0 = red16(p0);
        p1 = red16(p1);
        if (tx == 0 && grow < nrows) {
            out[(size_t)grow * 2 + 0] = p0 + cb0;
            out[(size_t)grow * 2 + 1] = p1 + cb1;
        }
    }
}

// ---------------------------------------------------------------------------
// Host launcher
// ---------------------------------------------------------------------------
extern "C" void kernel_launch(void* const* d_in, const int* in_sizes, int n_in,
                              void* d_out, int out_size) {
    const int*   A_row  = (const int*)d_in[0];
    const int*   A_col  = (const int*)d_in[1];
    const float* A_val  = (const float*)d_in[2];
    const int*   X_row  = (const int*)d_in[3];
    const int*   X_col  = (const int*)d_in[4];
    const float* X_val  = (const float*)d_in[5];
    const float* emb_W  = (const float*)d_in[6];
    const float* lin1_W = (const float*)d_in[7];
    const float* lin2_W = (const float*)d_in[8];
    const float* norm_g = (const float*)d_in[9];
    const float* norm_b = (const float*)d_in[10];
    const float* mlp_W  = (const float*)d_in[11];
    const float* mlp_b  = (const float*)d_in[12];
    const float* clf_W  = (const float*)d_in[13];
    const float* clf_b  = (const float*)d_in[14];
    float* out = (float*)d_out;

    int E    = in_sizes[0];
    int NNZ  = in_sizes[3];
    int V    = in_sizes[6] / H;
    int NDOC = out_size / 2;

    float *b1, *dc;
    __half *h1, *h2;
    int *aptr, *acur, *xptr, *xcur;
    int2 *acv, *xcv;
    cudaGetSymbolAddress((void**)&b1,   g_buf1);
    cudaGetSymbolAddress((void**)&dc,   g_doc);
    cudaGetSymbolAddress((void**)&h1,   g_h1);
    cudaGetSymbolAddress((void**)&h2,   g_h2);
    cudaGetSymbolAddress((void**)&aptr, gA_ptr);
    cudaGetSymbolAddress((void**)&acur, gA_cur);
    cudaGetSymbolAddress((void**)&acv,  gA_cv);
    cudaGetSymbolAddress((void**)&xptr, gX_ptr);
    cudaGetSymbolAddress((void**)&xcur, gX_cur);
    cudaGetSymbolAddress((void**)&xcv,  gX_cv);

    size_t smem = (size_t)2 * H * GPITCH * sizeof(float);
    cudaFuncSetAttribute(gemm_relu_kernel, cudaFuncAttributeMaxDynamicSharedMemorySize, (int)smem);
    cudaFuncSetAttribute(gemm_ln_kernel,   cudaFuncAttributeMaxDynamicSharedMemorySize, (int)smem);
    cudaFuncSetAttribute(gemm_clf_kernel,  cudaFuncAttributeMaxDynamicSharedMemorySize, (int)smem);

    // --- CSR build: 4 launches ---
    int zmax = (V > NDOC ? V : NDOC) + 1;
    int emax = (E > NNZ ? E : NNZ);
    zero_dual_kernel<<<(zmax + 255) / 256, 256>>>(aptr, V, xptr, NDOC);
    hist_dual_kernel<<<(emax + 255) / 256, 256>>>(A_row, E, aptr, X_row, NNZ, xptr);
    scan_dual_kernel<<<2, 1024>>>(aptr, acur, V, E, xptr, xcur, NDOC, NNZ);
    scatter_dual_kernel<<<(emax + 255) / 256, 256>>>(A_row, A_col, A_val, E, acur, acv,
                                                     X_row, X_col, X_val, NNZ, xcur, xcv);

    // emb -> half
    f2h_kernel<<<592, 256>>>(emb_W, h1, V * H / 4);

    int vblocks = (V + 127) / 128;
    int dblocks = (NDOC + 127) / 128;
    int spmmV_blocks = (V * 32 + 255) / 256;
    int spmmD_blocks = (NDOC * 32 + 255) / 256;

    // 1) b1 = A @ emb_h
    spmm_csr_kernel<<<spmmV_blocks, 256>>>(aptr, acv, h1, b1, V);
    // 2) h2 = half(relu(b1 @ lin1^T))
    gemm_relu_kernel<<<vblocks, 256, smem>>>(b1, lin1_W, h2, V);
    // 3) b1 = A @ h2
    spmm_csr_kernel<<<spmmV_blocks, 256>>>(aptr, acv, h2, b1, V);
    // 4) h2 = half( LN(0.3*emb + 0.7*relu(b1 @ lin2^T))*g + b + emb )
    gemm_ln_kernel<<<vblocks, 256, smem>>>(b1, lin2_W, emb_W, norm_g, norm_b, h2, V);
    // 5) dc = X @ h2   (wordsum includes +emb)
    spmm_csr_kernel<<<spmmD_blocks, 256>>>(xptr, xcv, h2, dc, NDOC);
    // 6) logits = relu(dc @ mlp^T + mlp_b) @ clf^T + clf_b
    gemm_clf_kernel<<<dblocks, 256, smem>>>(dc, mlp_W, mlp_b, clf_W, clf_b, out, NDOC);
}

// round 10
// speedup vs baseline: 1.8458x; 1.0180x over previous
#include <cuda_runtime.h>
#include <cuda_fp16.h>

#define H 128
#define GPITCH 132
#define VMAX 50048
#define DMAX 20096
#define EMAX 1600512
#define FULLM 0xffffffffu

// ---------------- static scratch (no allocation allowed) -------------------
__device__ float  g_buf1[(size_t)VMAX * H];    // fp32 SpMM outputs
__device__ float  g_doc [(size_t)DMAX * H];
__device__ __half g_h1  [(size_t)VMAX * H];    // half SpMM sources
__device__ __half g_h2  [(size_t)VMAX * H];

__device__ int  gA_ptr[VMAX + 1];
__device__ int  gA_cur[VMAX + 1];
__device__ int2 gA_cv[EMAX];                   // interleaved {col, val_bits}
__device__ int  gX_ptr[DMAX + 1];
__device__ int  gX_cur[DMAX + 1];
__device__ int2 gX_cv[EMAX];

// ---------------------------------------------------------------------------
// CSR build (per-matrix kernels so the X build can ride a second stream)
// ---------------------------------------------------------------------------
__global__ void zero_kernel(int* __restrict__ p, int n) {
    int i = blockIdx.x * blockDim.x + threadIdx.x;
    if (i < n) p[i] = 0;
}

__global__ void hist_kernel(const int* __restrict__ row, int nnz, int* __restrict__ cnt) {
    int i = blockIdx.x * blockDim.x + threadIdx.x;
    if (i < nnz) atomicAdd(cnt + __ldg(row + i), 1);
}

// Single block: sequential-tile exclusive scan (1024 threads/tile).
__global__ void scan_kernel(int* __restrict__ ptr, int* __restrict__ cur, int n, int nnz) {
    __shared__ int wsum[32];
    __shared__ int stotal;
    __shared__ int carry;
    int lane = threadIdx.x & 31, wid = threadIdx.x >> 5;
    if (threadIdx.x == 0) carry = 0;
    __syncthreads();

    int nt = (n + 1023) >> 10;
    for (int t = 0; t < nt; ++t) {
        int i = (t << 10) + threadIdx.x;
        int v = (i < n) ? ptr[i] : 0;
        int x = v;
#pragma unroll
        for (int off = 1; off < 32; off <<= 1) {
            int y = __shfl_up_sync(FULLM, x, off);
            if (lane >= off) x += y;
        }
        if (lane == 31) wsum[wid] = x;
        __syncthreads();
        if (wid == 0) {
            int w = wsum[lane];
            int xx = w;
#pragma unroll
            for (int off = 1; off < 32; off <<= 1) {
                int y = __shfl_up_sync(FULLM, xx, off);
                if (lane >= off) xx += y;
            }
            wsum[lane] = xx - w;
            if (lane == 31) stotal = xx;
        }
        __syncthreads();
        int excl = x - v + wsum[wid] + carry;
        if (i < n) { ptr[i] = excl; cur[i] = excl; }
        __syncthreads();
        if (threadIdx.x == 0) carry += stotal;
        __syncthreads();
    }
    if (threadIdx.x == 0) { ptr[n] = nnz; cur[n] = nnz; }
}

__global__ void scatter_kernel(const int* __restrict__ row, const int* __restrict__ col,
                               const float* __restrict__ val, int nnz,
                               int* __restrict__ cur, int2* __restrict__ cv) {
    int i = blockIdx.x * blockDim.x + threadIdx.x;
    if (i < nnz) {
        int r = __ldg(row + i);
        int p = atomicAdd(cur + r, 1);
        cv[p] = make_int2(__ldg(col + i), __float_as_int(__ldg(val + i)));
    }
}

// fp32 -> fp16 convert (float4 -> 4 halves)
__global__ void f2h_kernel(const float* __restrict__ src, __half* __restrict__ dst, int n4) {
    int i = blockIdx.x * blockDim.x + threadIdx.x;
    for (; i < n4; i += gridDim.x * blockDim.x) {
        float4 f = ((const float4*)src)[i];
        __half2 h0 = __floats2half2_rn(f.x, f.y);
        __half2 h1 = __floats2half2_rn(f.z, f.w);
        uint2 u;
        u.x = *(unsigned*)&h0;
        u.y = *(unsigned*)&h1;
        ((uint2*)dst)[i] = u;
    }
}

// ---------------------------------------------------------------------------
// Gather SpMM over CSR (half source, fp32 accumulate):
// one warp per row, lane handles 4 columns (8B half gather -> float4 acc)
// ---------------------------------------------------------------------------
__device__ __forceinline__ void spmm_edge(float4& acc, const __half* __restrict__ src,
                                          int c, float v, int lane) {
    uint2 u = __ldg(((const uint2*)(src + (size_t)c * H)) + lane);
    __half2 h0 = *(__half2*)&u.x;
    __half2 h1 = *(__half2*)&u.y;
    float2 f0 = __half22float2(h0);
    float2 f1 = __half22float2(h1);
    acc.x += v * f0.x; acc.y += v * f0.y;
    acc.z += v * f1.x; acc.w += v * f1.y;
}

__global__ void spmm_csr_kernel(const int* __restrict__ ptr, const int2* __restrict__ cv,
                                const __half* __restrict__ src,
                                float* __restrict__ dst, int nrows) {
    int w = (blockIdx.x * blockDim.x + threadIdx.x) >> 5;
    if (w >= nrows) return;
    int lane = threadIdx.x & 31;
    int beg = __ldg(ptr + w);
    int end = __ldg(ptr + w + 1);
    float4 acc = make_float4(0.f, 0.f, 0.f, 0.f);

    int base = beg;
    for (; base + 32 <= end; base += 32) {
        int2 e = __ldg(cv + base + lane);
        int c = e.x;
        float v = __int_as_float(e.y);
#pragma unroll 8
        for (int j = 0; j < 32; ++j) {
            int   cj = __shfl_sync(FULLM, c, j);
            float vj = __shfl_sync(FULLM, v, j);
            spmm_edge(acc, src, cj, vj, lane);
        }
    }
    if (base < end) {
        int n = end - base;
        int c = 0; float v = 0.f;
        if (base + lane < end) {
            int2 e = __ldg(cv + base + lane);
            c = e.x;
            v = __int_as_float(e.y);
        }
        int j = 0;
        for (; j + 4 <= n; j += 4) {
#pragma unroll
            for (int q = 0; q < 4; ++q) {
                int   cj = __shfl_sync(FULLM, c, j + q);
                float vj = __shfl_sync(FULLM, v, j + q);
                spmm_edge(acc, src, cj, vj, lane);
            }
        }
        for (; j < n; ++j) {
            int   cj = __shfl_sync(FULLM, c, j);
            float vj = __shfl_sync(FULLM, v, j);
            spmm_edge(acc, src, cj, vj, lane);
        }
    }
    ((float4*)(dst + (size_t)w * H))[lane] = acc;
}

// ---------------------------------------------------------------------------
// GEMM mainloop: 128x128 tile, 256 thr, 8x8 micro-tiles (fp32 in)
// ---------------------------------------------------------------------------
__device__ __forceinline__ void gemm_mainloop(const float* __restrict__ A, int nrows, int row0,
                                              const float* __restrict__ W,
                                              float* sA, float* sW,
                                              float acc[8][8]) {
    int tid = threadIdx.x;
#pragma unroll
    for (int it = 0; it < 16; ++it) {
        int idx = it * 256 + tid;
        int r   = idx & 127;
        int k4  = idx >> 7;
        int grow = row0 + r;
        float4 a = make_float4(0.f, 0.f, 0.f, 0.f);
        if (grow < nrows) a = *(const float4*)(A + (size_t)grow * H + k4 * 4);
        sA[(4 * k4 + 0) * GPITCH + r] = a.x;
        sA[(4 * k4 + 1) * GPITCH + r] = a.y;
        sA[(4 * k4 + 2) * GPITCH + r] = a.z;
        sA[(4 * k4 + 3) * GPITCH + r] = a.w;
        float4 wv = *(const float4*)(W + (size_t)r * H + k4 * 4);
        sW[(4 * k4 + 0) * GPITCH + r] = wv.x;
        sW[(4 * k4 + 1) * GPITCH + r] = wv.y;
        sW[(4 * k4 + 2) * GPITCH + r] = wv.z;
        sW[(4 * k4 + 3) * GPITCH + r] = wv.w;
    }
    __syncthreads();

    int tx = tid & 15, ty = tid >> 4;
#pragma unroll 4
    for (int k = 0; k < H; ++k) {
        const float* pa = sA + k * GPITCH + (ty << 3);
        const float* pb = sW + k * GPITCH + (tx << 3);
        float4 a0 = *(const float4*)(pa);
        float4 a1 = *(const float4*)(pa + 4);
        float4 b0 = *(const float4*)(pb);
        float4 b1 = *(const float4*)(pb + 4);
        float av[8] = {a0.x, a0.y, a0.z, a0.w, a1.x, a1.y, a1.z, a1.w};
        float bv[8] = {b0.x, b0.y, b0.z, b0.w, b1.x, b1.y, b1.z, b1.w};
#pragma unroll
        for (int i = 0; i < 8; ++i)
#pragma unroll
            for (int j = 0; j < 8; ++j)
                acc[i][j] += av[i] * bv[j];
    }
}

__device__ __forceinline__ float red16(float v) {
#pragma unroll
    for (int off = 8; off > 0; off >>= 1)
        v += __shfl_xor_sync(FULLM, v, off, 16);
    return v;
}

// pack 8 floats -> 8 halves (16B) and store
__device__ __forceinline__ void store_half8(__half* dst, const float* o) {
    __half2 h0 = __floats2half2_rn(o[0], o[1]);
    __half2 h1 = __floats2half2_rn(o[2], o[3]);
    __half2 h2 = __floats2half2_rn(o[4], o[5]);
    __half2 h3 = __floats2half2_rn(o[6], o[7]);
    uint4 u;
    u.x = *(unsigned*)&h0; u.y = *(unsigned*)&h1;
    u.z = *(unsigned*)&h2; u.w = *(unsigned*)&h3;
    *(uint4*)dst = u;
}

// out_h = half(relu(A @ W^T))
__global__ void gemm_relu_kernel(const float* __restrict__ A, const float* __restrict__ W,
                                 __half* __restrict__ out, int nrows) {
    extern __shared__ float smem[];
    float* sA = smem;
    float* sW = smem + H * GPITCH;
    float acc[8][8];
#pragma unroll
    for (int i = 0; i < 8; ++i)
#pragma unroll
        for (int j = 0; j < 8; ++j) acc[i][j] = 0.f;

    int row0 = blockIdx.x * 128;
    gemm_mainloop(A, nrows, row0, W, sA, sW, acc);

    int tid = threadIdx.x, tx = tid & 15, ty = tid >> 4;
#pragma unroll
    for (int i = 0; i < 8; ++i) {
        int grow = row0 + (ty << 3) + i;
        if (grow < nrows) {
            float o[8];
#pragma unroll
            for (int j = 0; j < 8; ++j) o[j] = fmaxf(acc[i][j], 0.f);
            store_half8(out + (size_t)grow * H + (tx << 3), o);
        }
    }
}

// out_h = half( LN(0.3*emb + 0.7*relu(A @ W^T))*g + b + emb )
__global__ void gemm_ln_kernel(const float* __restrict__ A, const float* __restrict__ W,
                               const float* __restrict__ emb,
                               const float* __restrict__ ng, const float* __restrict__ nb,
                               __half* __restrict__ out, int nrows) {
    extern __shared__ float smem[];
    float* sA = smem;
    float* sW = smem + H * GPITCH;
    float acc[8][8];
#pragma unroll
    for (int i = 0; i < 8; ++i)
#pragma unroll
        for (int j = 0; j < 8; ++j) acc[i][j] = 0.f;

    int row0 = blockIdx.x * 128;
    gemm_mainloop(A, nrows, row0, W, sA, sW, acc);

    int tid = threadIdx.x, tx = tid & 15, ty = tid >> 4;
    int c0 = tx << 3;
    float4 g0 = *(const float4*)(ng + c0);
    float4 g1 = *(const float4*)(ng + c0 + 4);
    float4 bb0 = *(const float4*)(nb + c0);
    float4 bb1 = *(const float4*)(nb + c0 + 4);
    float gv[8] = {g0.x, g0.y, g0.z, g0.w, g1.x, g1.y, g1.z, g1.w};
    float bv[8] = {bb0.x, bb0.y, bb0.z, bb0.w, bb1.x, bb1.y, bb1.z, bb1.w};

#pragma unroll
    for (int i = 0; i < 8; ++i) {
        int grow = row0 + (ty << 3) + i;
        bool valid = (grow < nrows);
        float4 e0 = make_float4(0.f, 0.f, 0.f, 0.f), e1 = e0;
        if (valid) {
            e0 = *(const float4*)(emb + (size_t)grow * H + c0);
            e1 = *(const float4*)(emb + (size_t)grow * H + c0 + 4);
        }
        float ev[8] = {e0.x, e0.y, e0.z, e0.w, e1.x, e1.y, e1.z, e1.w};
        float h[8];
        float s = 0.f;
#pragma unroll
        for (int j = 0; j < 8; ++j) {
            h[j] = 0.3f * ev[j] + 0.7f * fmaxf(acc[i][j], 0.f);
            s += h[j];
        }
        float mu = red16(s) * (1.f / 128.f);
        float ss = 0.f;
#pragma unroll
        for (int j = 0; j < 8; ++j) {
            h[j] -= mu;
            ss += h[j] * h[j];
        }
        float var = red16(ss) * (1.f / 128.f);
        float rstd = rsqrtf(var + 1e-5f);
        if (valid) {
            float o[8];
#pragma unroll
            for (int j = 0; j < 8; ++j)
                o[j] = h[j] * rstd * gv[j] + bv[j] + ev[j];
            store_half8(out + (size_t)grow * H + c0, o);
        }
    }
}

// logits = relu(A @ mlpW^T + mlp_b) @ clfW^T + clf_b
__global__ void gemm_clf_kernel(const float* __restrict__ A, const float* __restrict__ W,
                                const float* __restrict__ mlp_b,
                                const float* __restrict__ clf_W, const float* __restrict__ clf_b,
                                float* __restrict__ out, int nrows) {
    extern __shared__ float smem[];
    float* sA = smem;
    float* sW = smem + H * GPITCH;
    float acc[8][8];
#pragma unroll
    for (int i = 0; i < 8; ++i)
#pragma unroll
        for (int j = 0; j < 8; ++j) acc[i][j] = 0.f;

    int row0 = blockIdx.x * 128;
    gemm_mainloop(A, nrows, row0, W, sA, sW, acc);

    int tid = threadIdx.x, tx = tid & 15, ty = tid >> 4;
    int c0 = tx << 3;
    float4 mb0 = *(const float4*)(mlp_b + c0);
    float4 mb1 = *(const float4*)(mlp_b + c0 + 4);
    float bias[8] = {mb0.x, mb0.y, mb0.z, mb0.w, mb1.x, mb1.y, mb1.z, mb1.w};
    float4 w00 = *(const float4*)(clf_W + c0);
    float4 w01 = *(const float4*)(clf_W + c0 + 4);
    float4 w10 = *(const float4*)(clf_W + H + c0);
    float4 w11 = *(const float4*)(clf_W + H + c0 + 4);
    float cv0[8] = {w00.x, w00.y, w00.z, w00.w, w01.x, w01.y, w01.z, w01.w};
    float cv1[8] = {w10.x, w10.y, w10.z, w10.w, w11.x, w11.y, w11.z, w11.w};
    float cb0 = __ldg(clf_b), cb1 = __ldg(clf_b + 1);

#pragma unroll
    for (int i = 0; i < 8; ++i) {
        int grow = row0 + (ty << 3) + i;
        float p0 = 0.f, p1 = 0.f;
#pragma unroll
        for (int j = 0; j < 8; ++j) {
            float hv = fmaxf(acc[i][j] + bias[j], 0.f);
            p0 += hv * cv0[j];
            p1 += hv * cv1[j];
        }
        p0 = red16(p0);
        p1 = red16(p1);
        if (tx == 0 && grow < nrows) {
            out[(size_t)grow * 2 + 0] = p0 + cb0;
            out[(size_t)grow * 2 + 1] = p1 + cb1;
        }
    }
}

// ---------------------------------------------------------------------------
// Host launcher — fork-join: CSR-X build + f2h on a side stream, hidden
// under the CSR-A -> SpMM -> GEMM critical path.
// ---------------------------------------------------------------------------
extern "C" void kernel_launch(void* const* d_in, const int* in_sizes, int n_in,
                              void* d_out, int out_size) {
    const int*   A_row  = (const int*)d_in[0];
    const int*   A_col  = (const int*)d_in[1];
    const float* A_val  = (const float*)d_in[2];
    const int*   X_row  = (const int*)d_in[3];
    const int*   X_col  = (const int*)d_in[4];
    const float* X_val  = (const float*)d_in[5];
    const float* emb_W  = (const float*)d_in[6];
    const float* lin1_W = (const float*)d_in[7];
    const float* lin2_W = (const float*)d_in[8];
    const float* norm_g = (const float*)d_in[9];
    const float* norm_b = (const float*)d_in[10];
    const float* mlp_W  = (const float*)d_in[11];
    const float* mlp_b  = (const float*)d_in[12];
    const float* clf_W  = (const float*)d_in[13];
    const float* clf_b  = (const float*)d_in[14];
    float* out = (float*)d_out;

    int E    = in_sizes[0];
    int NNZ  = in_sizes[3];
    int V    = in_sizes[6] / H;
    int NDOC = out_size / 2;

    float *b1, *dc;
    __half *h1, *h2;
    int *aptr, *acur, *xptr, *xcur;
    int2 *acv, *xcv;
    cudaGetSymbolAddress((void**)&b1,   g_buf1);
    cudaGetSymbolAddress((void**)&dc,   g_doc);
    cudaGetSymbolAddress((void**)&h1,   g_h1);
    cudaGetSymbolAddress((void**)&h2,   g_h2);
    cudaGetSymbolAddress((void**)&aptr, gA_ptr);
    cudaGetSymbolAddress((void**)&acur, gA_cur);
    cudaGetSymbolAddress((void**)&acv,  gA_cv);
    cudaGetSymbolAddress((void**)&xptr, gX_ptr);
    cudaGetSymbolAddress((void**)&xcur, gX_cur);
    cudaGetSymbolAddress((void**)&xcv,  gX_cv);

    size_t smem = (size_t)2 * H * GPITCH * sizeof(float);
    cudaFuncSetAttribute(gemm_relu_kernel, cudaFuncAttributeMaxDynamicSharedMemorySize, (int)smem);
    cudaFuncSetAttribute(gemm_ln_kernel,   cudaFuncAttributeMaxDynamicSharedMemorySize, (int)smem);
    cudaFuncSetAttribute(gemm_clf_kernel,  cudaFuncAttributeMaxDynamicSharedMemorySize, (int)smem);

    // Side stream + events (created once; the per-call work stays identical,
    // so every capture produces the same graph).
    static cudaStream_t s2 = nullptr;
    static cudaEvent_t evFork = nullptr, evF2H = nullptr, evX = nullptr;
    if (!s2) {
        cudaStreamCreateWithFlags(&s2, cudaStreamNonBlocking);
        cudaEventCreateWithFlags(&evFork, cudaEventDisableTiming);
        cudaEventCreateWithFlags(&evF2H,  cudaEventDisableTiming);
        cudaEventCreateWithFlags(&evX,    cudaEventDisableTiming);
    }

    // ---- fork: side stream does f2h(emb) then the full CSR-X build ----
    cudaEventRecord(evFork, 0);
    cudaStreamWaitEvent(s2, evFork, 0);

    f2h_kernel<<<592, 256, 0, s2>>>(emb_W, h1, V * H / 4);
    cudaEventRecord(evF2H, s2);
    zero_kernel<<<(NDOC + 256) / 256, 256, 0, s2>>>(xptr, NDOC);
    hist_kernel<<<(NNZ + 255) / 256, 256, 0, s2>>>(X_row, NNZ, xptr);
    scan_kernel<<<1, 1024, 0, s2>>>(xptr, xcur, NDOC, NNZ);
    scatter_kernel<<<(NNZ + 255) / 256, 256, 0, s2>>>(X_row, X_col, X_val, NNZ, xcur, xcv);
    cudaEventRecord(evX, s2);

    // ---- main stream: CSR-A build ----
    zero_kernel<<<(V + 256) / 256, 256>>>(aptr, V);
    hist_kernel<<<(E + 255) / 256, 256>>>(A_row, E, aptr);
    scan_kernel<<<1, 1024>>>(aptr, acur, V, E);
    scatter_kernel<<<(E + 255) / 256, 256>>>(A_row, A_col, A_val, E, acur, acv);

    int vblocks = (V + 127) / 128;
    int dblocks = (NDOC + 127) / 128;
    int spmmV_blocks = (V * 32 + 255) / 256;
    int spmmD_blocks = (NDOC * 32 + 255) / 256;

    // 1) b1 = A @ emb_h   (needs f2h from side stream)
    cudaStreamWaitEvent(0, evF2H, 0);
    spmm_csr_kernel<<<spmmV_blocks, 256>>>(aptr, acv, h1, b1, V);
    // 2) h2 = half(relu(b1 @ lin1^T))
    gemm_relu_kernel<<<vblocks, 256, smem>>>(b1, lin1_W, h2, V);
    // 3) b1 = A @ h2
    spmm_csr_kernel<<<spmmV_blocks, 256>>>(aptr, acv, h2, b1, V);
    // 4) h2 = half( LN(0.3*emb + 0.7*relu(b1 @ lin2^T))*g + b + emb )
    gemm_ln_kernel<<<vblocks, 256, smem>>>(b1, lin2_W, emb_W, norm_g, norm_b, h2, V);
    // 5) dc = X @ h2   (needs CSR-X from side stream; wordsum includes +emb)
    cudaStreamWaitEvent(0, evX, 0);
    spmm_csr_kernel<<<spmmD_blocks, 256>>>(xptr, xcv, h2, dc, NDOC);
    // 6) logits = relu(dc @ mlp^T + mlp_b) @ clf^T + clf_b
    gemm_clf_kernel<<<dblocks, 256, smem>>>(dc, mlp_W, mlp_b, clf_W, clf_b, out, NDOC);
}

// round 15
// speedup vs baseline: 1.9248x; 1.0428x over previous
#include <cuda_runtime.h>
#include <cuda_fp16.h>

#define H 128
#define GPITCH 132
#define VMAX 50048
#define DMAX 20096
#define EMAX 1600512
#define FULLM 0xffffffffu

// ---------------- static scratch (no allocation allowed) -------------------
__device__ float  g_buf1[(size_t)VMAX * H];    // fp32 SpMM outputs
__device__ float  g_doc [(size_t)DMAX * H];
__device__ __half g_h1  [(size_t)VMAX * H];    // half SpMM sources
__device__ __half g_h2  [(size_t)VMAX * H];

__device__ int  gA_ptr[VMAX + 1];
__device__ int  gA_cur[VMAX + 1];
__device__ int2 gA_cv[EMAX];                   // interleaved {col, val_bits}
__device__ int  gX_ptr[DMAX + 1];
__device__ int  gX_cur[DMAX + 1];
__device__ int2 gX_cv[EMAX];
__device__ int  g_bsumA[64];
__device__ int  g_bsumX[64];

// ---------------------------------------------------------------------------
// CSR build kernels
// ---------------------------------------------------------------------------
__global__ void zero_kernel(int* __restrict__ p, int n) {
    int i = blockIdx.x * blockDim.x + threadIdx.x;
    if (i < n) p[i] = 0;
}

__global__ void hist_kernel(const int* __restrict__ row, int nnz, int* __restrict__ cnt) {
    int i = blockIdx.x * blockDim.x + threadIdx.x;
    if (i < nnz) atomicAdd(cnt + __ldg(row + i), 1);
}

// Parallel 3-phase exclusive scan (shuffle-based).
__global__ void scan1_kernel(int* __restrict__ ptr, int* __restrict__ bsum, int n) {
    __shared__ int wsum[32];
    int i = blockIdx.x * 1024 + threadIdx.x;
    int lane = threadIdx.x & 31, wid = threadIdx.x >> 5;
    int v = (i < n) ? ptr[i] : 0;
    int x = v;
#pragma unroll
    for (int off = 1; off < 32; off <<= 1) {
        int y = __shfl_up_sync(FULLM, x, off);
        if (lane >= off) x += y;
    }
    if (lane == 31) wsum[wid] = x;
    __syncthreads();
    if (wid == 0) {
        int w = wsum[lane];
        int xx = w;
#pragma unroll
        for (int off = 1; off < 32; off <<= 1) {
            int y = __shfl_up_sync(FULLM, xx, off);
            if (lane >= off) xx += y;
        }
        wsum[lane] = xx - w;                 // exclusive warp offsets
    }
    __syncthreads();
    int excl = x - v + wsum[wid];
    if (i < n) ptr[i] = excl;
    if (threadIdx.x == 1023) bsum[blockIdx.x] = excl + v;   // block total
}

__global__ void scan2_kernel(int* __restrict__ bsum, int nb) {
    __shared__ int s[64];
    int t = threadIdx.x;
    int v = (t < nb) ? bsum[t] : 0;
    s[t] = v;
    __syncthreads();
#pragma unroll
    for (int off = 1; off < 64; off <<= 1) {
        int u = (t >= off) ? s[t - off] : 0;
        __syncthreads();
        s[t] += u;
        __syncthreads();
    }
    if (t < nb) bsum[t] = s[t] - v;          // exclusive
}

__global__ void scan3_kernel(int* __restrict__ ptr, int* __restrict__ cur,
                             const int* __restrict__ bsum, int n, int nnz) {
    int i = blockIdx.x * 1024 + threadIdx.x;
    if (i < n) {
        int p = ptr[i] + bsum[blockIdx.x];
        ptr[i] = p;
        cur[i] = p;
    }
    if (i == 0) { ptr[n] = nnz; cur[n] = nnz; }
}

__global__ void scatter_kernel(const int* __restrict__ row, const int* __restrict__ col,
                               const float* __restrict__ val, int nnz,
                               int* __restrict__ cur, int2* __restrict__ cv) {
    int i = blockIdx.x * blockDim.x + threadIdx.x;
    if (i < nnz) {
        int r = __ldg(row + i);
        int p = atomicAdd(cur + r, 1);
        cv[p] = make_int2(__ldg(col + i), __float_as_int(__ldg(val + i)));
    }
}

// fp32 -> fp16 convert (float4 -> 4 halves)
__global__ void f2h_kernel(const float* __restrict__ src, __half* __restrict__ dst, int n4) {
    int i = blockIdx.x * blockDim.x + threadIdx.x;
    for (; i < n4; i += gridDim.x * blockDim.x) {
        float4 f = ((const float4*)src)[i];
        __half2 h0 = __floats2half2_rn(f.x, f.y);
        __half2 h1 = __floats2half2_rn(f.z, f.w);
        uint2 u;
        u.x = *(unsigned*)&h0;
        u.y = *(unsigned*)&h1;
        ((uint2*)dst)[i] = u;
    }
}

// ---------------------------------------------------------------------------
// Gather SpMM over CSR (half source, fp32 accumulate)
// ---------------------------------------------------------------------------
__device__ __forceinline__ void spmm_edge(float4& acc, const __half* __restrict__ src,
                                          int c, float v, int lane) {
    uint2 u = __ldg(((const uint2*)(src + (size_t)c * H)) + lane);
    __half2 h0 = *(__half2*)&u.x;
    __half2 h1 = *(__half2*)&u.y;
    float2 f0 = __half22float2(h0);
    float2 f1 = __half22float2(h1);
    acc.x += v * f0.x; acc.y += v * f0.y;
    acc.z += v * f1.x; acc.w += v * f1.y;
}

__global__ void spmm_csr_kernel(const int* __restrict__ ptr, const int2* __restrict__ cv,
                                const __half* __restrict__ src,
                                float* __restrict__ dst, int nrows) {
    int w = (blockIdx.x * blockDim.x + threadIdx.x) >> 5;
    if (w >= nrows) return;
    int lane = threadIdx.x & 31;
    int beg = __ldg(ptr + w);
    int end = __ldg(ptr + w + 1);
    float4 acc = make_float4(0.f, 0.f, 0.f, 0.f);

    int base = beg;
    for (; base + 32 <= end; base += 32) {
        int2 e = __ldg(cv + base + lane);
        int c = e.x;
        float v = __int_as_float(e.y);
#pragma unroll 8
        for (int j = 0; j < 32; ++j) {
            int   cj = __shfl_sync(FULLM, c, j);
            float vj = __shfl_sync(FULLM, v, j);
            spmm_edge(acc, src, cj, vj, lane);
        }
    }
    if (base < end) {
        int n = end - base;
        int c = 0; float v = 0.f;
        if (base + lane < end) {
            int2 e = __ldg(cv + base + lane);
            c = e.x;
            v = __int_as_float(e.y);
        }
        int j = 0;
        for (; j + 4 <= n; j += 4) {
#pragma unroll
            for (int q = 0; q < 4; ++q) {
                int   cj = __shfl_sync(FULLM, c, j + q);
                float vj = __shfl_sync(FULLM, v, j + q);
                spmm_edge(acc, src, cj, vj, lane);
            }
        }
        for (; j < n; ++j) {
            int   cj = __shfl_sync(FULLM, c, j);
            float vj = __shfl_sync(FULLM, v, j);
            spmm_edge(acc, src, cj, vj, lane);
        }
    }
    ((float4*)(dst + (size_t)w * H))[lane] = acc;
}

// ---------------------------------------------------------------------------
// Packed-f32x2 helpers (sm_103a FFMA2: only reachable via PTX fma.rn.f32x2)
// ---------------------------------------------------------------------------
__device__ __forceinline__ void fma2(unsigned long long& d,
                                     unsigned long long a, unsigned long long b) {
    asm("fma.rn.f32x2 %0, %1, %2, %0;" : "+l"(d) : "l"(a), "l"(b));
}
__device__ __forceinline__ unsigned long long dup_f32(float a) {
    unsigned long long r;
    asm("mov.b64 %0, {%1, %1};" : "=l"(r) : "f"(a));
    return r;
}
__device__ __forceinline__ void unpack_row(const unsigned long long* a2, float* o) {
#pragma unroll
    for (int j = 0; j < 4; ++j)
        asm("mov.b64 {%0, %1}, %2;" : "=f"(o[2 * j]), "=f"(o[2 * j + 1]) : "l"(a2[j]));
}

// ---------------------------------------------------------------------------
// GEMM mainloop: 128x128 tile, 256 thr, 8x8 micro-tiles, packed f32x2 FMA
// ---------------------------------------------------------------------------
__device__ __forceinline__ void gemm_mainloop(const float* __restrict__ A, int nrows, int row0,
                                              const float* __restrict__ W,
                                              float* sA, float* sW,
                                              unsigned long long acc2[8][4]) {
    int tid = threadIdx.x;
#pragma unroll
    for (int it = 0; it < 16; ++it) {
        int idx = it * 256 + tid;
        int r   = idx & 127;
        int k4  = idx >> 7;
        int grow = row0 + r;
        float4 a = make_float4(0.f, 0.f, 0.f, 0.f);
        if (grow < nrows) a = *(const float4*)(A + (size_t)grow * H + k4 * 4);
        sA[(4 * k4 + 0) * GPITCH + r] = a.x;
        sA[(4 * k4 + 1) * GPITCH + r] = a.y;
        sA[(4 * k4 + 2) * GPITCH + r] = a.z;
        sA[(4 * k4 + 3) * GPITCH + r] = a.w;
        float4 wv = *(const float4*)(W + (size_t)r * H + k4 * 4);
        sW[(4 * k4 + 0) * GPITCH + r] = wv.x;
        sW[(4 * k4 + 1) * GPITCH + r] = wv.y;
        sW[(4 * k4 + 2) * GPITCH + r] = wv.z;
        sW[(4 * k4 + 3) * GPITCH + r] = wv.w;
    }
    __syncthreads();

    int tx = tid & 15, ty = tid >> 4;
#pragma unroll 4
    for (int k = 0; k < H; ++k) {
        const float* pa = sA + k * GPITCH + (ty << 3);
        const float* pb = sW + k * GPITCH + (tx << 3);
        float4 a0 = *(const float4*)(pa);
        float4 a1 = *(const float4*)(pa + 4);
        ulonglong2 b0 = *(const ulonglong2*)(pb);
        ulonglong2 b1 = *(const ulonglong2*)(pb + 4);
        float av[8] = {a0.x, a0.y, a0.z, a0.w, a1.x, a1.y, a1.z, a1.w};
        unsigned long long bp[4] = {b0.x, b0.y, b1.x, b1.y};
#pragma unroll
        for (int i = 0; i < 8; ++i) {
            unsigned long long ad = dup_f32(av[i]);
#pragma unroll
            for (int j = 0; j < 4; ++j)
                fma2(acc2[i][j], ad, bp[j]);
        }
    }
}

__device__ __forceinline__ float red16(float v) {
#pragma unroll
    for (int off = 8; off > 0; off >>= 1)
        v += __shfl_xor_sync(FULLM, v, off, 16);
    return v;
}

// pack 8 floats -> 8 halves (16B) and store
__device__ __forceinline__ void store_half8(__half* dst, const float* o) {
    __half2 h0 = __floats2half2_rn(o[0], o[1]);
    __half2 h1 = __floats2half2_rn(o[2], o[3]);
    __half2 h2 = __floats2half2_rn(o[4], o[5]);
    __half2 h3 = __floats2half2_rn(o[6], o[7]);
    uint4 u;
    u.x = *(unsigned*)&h0; u.y = *(unsigned*)&h1;
    u.z = *(unsigned*)&h2; u.w = *(unsigned*)&h3;
    *(uint4*)dst = u;
}

#define ACC_INIT  unsigned long long acc2[8][4]; \
    _Pragma("unroll") for (int i = 0; i < 8; ++i) \
    _Pragma("unroll") for (int j = 0; j < 4; ++j) acc2[i][j] = 0ull;

// out_h = half(relu(A @ W^T))
__global__ void gemm_relu_kernel(const float* __restrict__ A, const float* __restrict__ W,
                                 __half* __restrict__ out, int nrows) {
    extern __shared__ float smem[];
    float* sA = smem;
    float* sW = smem + H * GPITCH;
    ACC_INIT
    int row0 = blockIdx.x * 128;
    gemm_mainloop(A, nrows, row0, W, sA, sW, acc2);

    int tid = threadIdx.x, tx = tid & 15, ty = tid >> 4;
#pragma unroll
    for (int i = 0; i < 8; ++i) {
        int grow = row0 + (ty << 3) + i;
        if (grow < nrows) {
            float o[8];
            unpack_row(acc2[i], o);
#pragma unroll
            for (int j = 0; j < 8; ++j) o[j] = fmaxf(o[j], 0.f);
            store_half8(out + (size_t)grow * H + (tx << 3), o);
        }
    }
}

// out_h = half( LN(0.3*emb + 0.7*relu(A @ W^T))*g + b + emb )
__global__ void gemm_ln_kernel(const float* __restrict__ A, const float* __restrict__ W,
                               const float* __restrict__ emb,
                               const float* __restrict__ ng, const float* __restrict__ nb,
                               __half* __restrict__ out, int nrows) {
    extern __shared__ float smem[];
    float* sA = smem;
    float* sW = smem + H * GPITCH;
    ACC_INIT
    int row0 = blockIdx.x * 128;
    gemm_mainloop(A, nrows, row0, W, sA, sW, acc2);

    int tid = threadIdx.x, tx = tid & 15, ty = tid >> 4;
    int c0 = tx << 3;
    float4 g0 = *(const float4*)(ng + c0);
    float4 g1 = *(const float4*)(ng + c0 + 4);
    float4 bb0 = *(const float4*)(nb + c0);
    float4 bb1 = *(const float4*)(nb + c0 + 4);
    float gv[8] = {g0.x, g0.y, g0.z, g0.w, g1.x, g1.y, g1.z, g1.w};
    float bv[8] = {bb0.x, bb0.y, bb0.z, bb0.w, bb1.x, bb1.y, bb1.z, bb1.w};

#pragma unroll
    for (int i = 0; i < 8; ++i) {
        int grow = row0 + (ty << 3) + i;
        bool valid = (grow < nrows);
        float4 e0 = make_float4(0.f, 0.f, 0.f, 0.f), e1 = e0;
        if (valid) {
            e0 = *(const float4*)(emb + (size_t)grow * H + c0);
            e1 = *(const float4*)(emb + (size_t)grow * H + c0 + 4);
        }
        float ev[8] = {e0.x, e0.y, e0.z, e0.w, e1.x, e1.y, e1.z, e1.w};
        float h[8];
        unpack_row(acc2[i], h);
        float s = 0.f;
#pragma unroll
        for (int j = 0; j < 8; ++j) {
            h[j] = 0.3f * ev[j] + 0.7f * fmaxf(h[j], 0.f);
            s += h[j];
        }
        float mu = red16(s) * (1.f / 128.f);
        float ss = 0.f;
#pragma unroll
        for (int j = 0; j < 8; ++j) {
            h[j] -= mu;
            ss += h[j] * h[j];
        }
        float var = red16(ss) * (1.f / 128.f);
        float rstd = rsqrtf(var + 1e-5f);
        if (valid) {
            float o[8];
#pragma unroll
            for (int j = 0; j < 8; ++j)
                o[j] = h[j] * rstd * gv[j] + bv[j] + ev[j];
            store_half8(out + (size_t)grow * H + c0, o);
        }
    }
}

// logits = relu(A @ mlpW^T + mlp_b) @ clfW^T + clf_b
__global__ void gemm_clf_kernel(const float* __restrict__ A, const float* __restrict__ W,
                                const float* __restrict__ mlp_b,
                                const float* __restrict__ clf_W, const float* __restrict__ clf_b,
                                float* __restrict__ out, int nrows) {
    extern __shared__ float smem[];
    float* sA = smem;
    float* sW = smem + H * GPITCH;
    ACC_INIT
    int row0 = blockIdx.x * 128;
    gemm_mainloop(A, nrows, row0, W, sA, sW, acc2);

    int tid = threadIdx.x, tx = tid & 15, ty = tid >> 4;
    int c0 = tx << 3;
    float4 mb0 = *(const float4*)(mlp_b + c0);
    float4 mb1 = *(const float4*)(mlp_b + c0 + 4);
    float bias[8] = {mb0.x, mb0.y, mb0.z, mb0.w, mb1.x, mb1.y, mb1.z, mb1.w};
    float4 w00 = *(const float4*)(clf_W + c0);
    float4 w01 = *(const float4*)(clf_W + c0 + 4);
    float4 w10 = *(const float4*)(clf_W + H + c0);
    float4 w11 = *(const float4*)(clf_W + H + c0 + 4);
    float cv0[8] = {w00.x, w00.y, w00.z, w00.w, w01.x, w01.y, w01.z, w01.w};
    float cv1[8] = {w10.x, w10.y, w10.z, w10.w, w11.x, w11.y, w11.z, w11.w};
    float cb0 = __ldg(clf_b), cb1 = __ldg(clf_b + 1);

#pragma unroll
    for (int i = 0; i < 8; ++i) {
        int grow = row0 + (ty << 3) + i;
        float h[8];
        unpack_row(acc2[i], h);
        float p0 = 0.f, p1 = 0.f;
#pragma unroll
        for (int j = 0; j < 8; ++j) {
            float hv = fmaxf(h[j] + bias[j], 0.f);
            p0 += hv * cv0[j];
            p1 += hv * cv1[j];
        }
        p0 = red16(p0);
        p1 = red16(p1);
        if (tx == 0 && grow < nrows) {
            out[(size_t)grow * 2 + 0] = p0 + cb0;
            out[(size_t)grow * 2 + 1] = p1 + cb1;
        }
    }
}

// ---------------------------------------------------------------------------
// Host launcher — fork-join kept (X build + f2h off critical path)
// ---------------------------------------------------------------------------
extern "C" void kernel_launch(void* const* d_in, const int* in_sizes, int n_in,
                              void* d_out, int out_size) {
    const int*   A_row  = (const int*)d_in[0];
    const int*   A_col  = (const int*)d_in[1];
    const float* A_val  = (const float*)d_in[2];
    const int*   X_row  = (const int*)d_in[3];
    const int*   X_col  = (const int*)d_in[4];
    const float* X_val  = (const float*)d_in[5];
    const float* emb_W  = (const float*)d_in[6];
    const float* lin1_W = (const float*)d_in[7];
    const float* lin2_W = (const float*)d_in[8];
    const float* norm_g = (const float*)d_in[9];
    const float* norm_b = (const float*)d_in[10];
    const float* mlp_W  = (const float*)d_in[11];
    const float* mlp_b  = (const float*)d_in[12];
    const float* clf_W  = (const float*)d_in[13];
    const float* clf_b  = (const float*)d_in[14];
    float* out = (float*)d_out;

    int E    = in_sizes[0];
    int NNZ  = in_sizes[3];
    int V    = in_sizes[6] / H;
    int NDOC = out_size / 2;

    float *b1, *dc;
    __half *h1, *h2;
    int *aptr, *acur, *xptr, *xcur, *bsA, *bsX;
    int2 *acv, *xcv;
    cudaGetSymbolAddress((void**)&b1,   g_buf1);
    cudaGetSymbolAddress((void**)&dc,   g_doc);
    cudaGetSymbolAddress((void**)&h1,   g_h1);
    cudaGetSymbolAddress((void**)&h2,   g_h2);
    cudaGetSymbolAddress((void**)&aptr, gA_ptr);
    cudaGetSymbolAddress((void**)&acur, gA_cur);
    cudaGetSymbolAddress((void**)&acv,  gA_cv);
    cudaGetSymbolAddress((void**)&xptr, gX_ptr);
    cudaGetSymbolAddress((void**)&xcur, gX_cur);
    cudaGetSymbolAddress((void**)&xcv,  gX_cv);
    cudaGetSymbolAddress((void**)&bsA,  g_bsumA);
    cudaGetSymbolAddress((void**)&bsX,  g_bsumX);

    size_t smem = (size_t)2 * H * GPITCH * sizeof(float);
    cudaFuncSetAttribute(gemm_relu_kernel, cudaFuncAttributeMaxDynamicSharedMemorySize, (int)smem);
    cudaFuncSetAttribute(gemm_ln_kernel,   cudaFuncAttributeMaxDynamicSharedMemorySize, (int)smem);
    cudaFuncSetAttribute(gemm_clf_kernel,  cudaFuncAttributeMaxDynamicSharedMemorySize, (int)smem);

    static cudaStream_t s2 = nullptr;
    static cudaEvent_t evFork = nullptr, evF2H = nullptr, evX = nullptr;
    if (!s2) {
        cudaStreamCreateWithFlags(&s2, cudaStreamNonBlocking);
        cudaEventCreateWithFlags(&evFork, cudaEventDisableTiming);
        cudaEventCreateWithFlags(&evF2H,  cudaEventDisableTiming);
        cudaEventCreateWithFlags(&evX,    cudaEventDisableTiming);
    }

    int nbA = (V + 1023) / 1024;
    int nbX = (NDOC + 1023) / 1024;

    // ---- fork: side stream does f2h(emb) then the full CSR-X build ----
    cudaEventRecord(evFork, 0);
    cudaStreamWaitEvent(s2, evFork, 0);

    f2h_kernel<<<592, 256, 0, s2>>>(emb_W, h1, V * H / 4);
    cudaEventRecord(evF2H, s2);
    zero_kernel<<<(NDOC + 255) / 256, 256, 0, s2>>>(xptr, NDOC);
    hist_kernel<<<(NNZ + 255) / 256, 256, 0, s2>>>(X_row, NNZ, xptr);
    scan1_kernel<<<nbX, 1024, 0, s2>>>(xptr, bsX, NDOC);
    scan2_kernel<<<1, 64, 0, s2>>>(bsX, nbX);
    scan3_kernel<<<nbX, 1024, 0, s2>>>(xptr, xcur, bsX, NDOC, NNZ);
    scatter_kernel<<<(NNZ + 255) / 256, 256, 0, s2>>>(X_row, X_col, X_val, NNZ, xcur, xcv);
    cudaEventRecord(evX, s2);

    // ---- main stream: CSR-A build (parallel scan) ----
    zero_kernel<<<(V + 255) / 256, 256>>>(aptr, V);
    hist_kernel<<<(E + 255) / 256, 256>>>(A_row, E, aptr);
    scan1_kernel<<<nbA, 1024>>>(aptr, bsA, V);
    scan2_kernel<<<1, 64>>>(bsA, nbA);
    scan3_kernel<<<nbA, 1024>>>(aptr, acur, bsA, V, E);
    scatter_kernel<<<(E + 255) / 256, 256>>>(A_row, A_col, A_val, E, acur, acv);

    int vblocks = (V + 127) / 128;
    int dblocks = (NDOC + 127) / 128;
    int spmmV_blocks = (V * 32 + 255) / 256;
    int spmmD_blocks = (NDOC * 32 + 255) / 256;

    // 1) b1 = A @ emb_h   (needs f2h from side stream)
    cudaStreamWaitEvent(0, evF2H, 0);
    spmm_csr_kernel<<<spmmV_blocks, 256>>>(aptr, acv, h1, b1, V);
    // 2) h2 = half(relu(b1 @ lin1^T))
    gemm_relu_kernel<<<vblocks, 256, smem>>>(b1, lin1_W, h2, V);
    // 3) b1 = A @ h2
    spmm_csr_kernel<<<spmmV_blocks, 256>>>(aptr, acv, h2, b1, V);
    // 4) h2 = half( LN(0.3*emb + 0.7*relu(b1 @ lin2^T))*g + b + emb )
    gemm_ln_kernel<<<vblocks, 256, smem>>>(b1, lin2_W, emb_W, norm_g, norm_b, h2, V);
    // 5) dc = X @ h2   (needs CSR-X from side stream; wordsum includes +emb)
    cudaStreamWaitEvent(0, evX, 0);
    spmm_csr_kernel<<<spmmD_blocks, 256>>>(xptr, xcv, h2, dc, NDOC);
    // 6) logits = relu(dc @ mlp^T + mlp_b) @ clf^T + clf_b
    gemm_clf_kernel<<<dblocks, 256, smem>>>(dc, mlp_W, mlp_b, clf_W, clf_b, out, NDOC);
}